// round 4
// baseline (speedup 1.0000x reference)
#include <cuda_runtime.h>
#include <math.h>

#define NN 50000
#define NE 800000
#define CDIM 128
#define NLAYER 4
#define NCLASS 40

typedef unsigned long long ull;

// ---------------- f32x2 packed-FMA helpers ----------------
#define PACKF2(out, lo, hi) asm("mov.b64 %0, {%1, %2};" : "=l"(out) : "f"(lo), "f"(hi))
#define UNPACKF2(lo, hi, in) asm("mov.b64 {%0, %1}, %2;" : "=f"(lo), "=f"(hi) : "l"(in))
__device__ __forceinline__ ull ffma2(ull a, ull b, ull c) {
    ull d;
    asm("fma.rn.f32x2 %0, %1, %2, %3;" : "=l"(d) : "l"(a), "l"(b), "l"(c));
    return d;
}

// ---------------- scratch (device globals; no allocation allowed) ----------------
__device__ int   g_is64;
__device__ int   g_deg[NN];
__device__ int   g_fill[NN];
__device__ int   g_rowptr[NN + 1];
__device__ float g_dinv[NN];
__device__ int   g_col[NE];
__device__ __align__(16) float g_ew[NE];
__device__ __align__(16) float g_hW[(size_t)NN * CDIM];
__device__ __align__(16) float g_H[(size_t)NLAYER * NN * CDIM];
__device__ __align__(16) float g_scores[(size_t)NN * NLAYER];

// ---------------- edge dtype detection ----------------
__global__ void detect_kernel(const void* ei) {
    const long long* p = (const long long*)ei;
    int ok = 1;
    for (int i = 0; i < 8; ++i) {
        long long v = p[i];
        if (v < 0 || v >= NN) ok = 0;
    }
    g_is64 = ok;
}

__device__ __forceinline__ int edge_src(const void* ei, int e) {
    return g_is64 ? (int)((const long long*)ei)[e] : ((const int*)ei)[e];
}
__device__ __forceinline__ int edge_dst(const void* ei, int e) {
    return g_is64 ? (int)((const long long*)ei)[NE + e] : ((const int*)ei)[NE + e];
}

// ---------------- CSR build ----------------
__global__ void zero_kernel() {
    int i = blockIdx.x * blockDim.x + threadIdx.x;
    if (i < NN) { g_deg[i] = 0; g_fill[i] = 0; }
}

__global__ void hist_kernel(const void* __restrict__ ei) {
    int e = blockIdx.x * blockDim.x + threadIdx.x;
    if (e < NE) {
        int d = edge_dst(ei, e);
        if ((unsigned)d < NN) atomicAdd(&g_deg[d], 1);
    }
}

// Fast single-block scan: serial chunk sums -> shuffle scan of 1024 partials
// -> serial write-back (re-reads g_deg from L2). 3 barriers total.
__global__ __launch_bounds__(1024) void scan_dinv_kernel() {
    __shared__ int wsum[32];
    const int CH = (NN + 1023) / 1024;   // 49
    int tid = threadIdx.x;
    int lane = tid & 31, wid = tid >> 5;
    int beg = tid * CH;
    int end = beg + CH; if (end > NN) end = NN;

    int s = 0;
    for (int i = beg; i < end; ++i) s += g_deg[i];

    int inc = s;
#pragma unroll
    for (int o = 1; o < 32; o <<= 1) {
        int t = __shfl_up_sync(0xffffffffu, inc, o);
        if (lane >= o) inc += t;
    }
    if (lane == 31) wsum[wid] = inc;
    __syncthreads();
    if (wid == 0) {
        int v = wsum[lane];
#pragma unroll
        for (int o = 1; o < 32; o <<= 1) {
            int t = __shfl_up_sync(0xffffffffu, v, o);
            if (lane >= o) v += t;
        }
        wsum[lane] = v;
    }
    __syncthreads();

    int run = (wid ? wsum[wid - 1] : 0) + (inc - s);  // exclusive prefix of this thread
    if (tid == 0) g_rowptr[0] = 0;
    for (int i = beg; i < end; ++i) {
        int v = g_deg[i];
        g_dinv[i] = rsqrtf(1.0f + (float)v);
        run += v;
        g_rowptr[i + 1] = run;
    }
}

__global__ void scatter_kernel(const void* __restrict__ ei) {
    int e = blockIdx.x * blockDim.x + threadIdx.x;
    if (e < NE) {
        int s = edge_src(ei, e);
        int d = edge_dst(ei, e);
        if ((unsigned)s < NN && (unsigned)d < NN) {
            int pos = g_rowptr[d] + atomicAdd(&g_fill[d], 1);
            g_col[pos] = s;
            g_ew[pos]  = g_dinv[s] * g_dinv[d];
        }
    }
}

// ---------------- GEMM with packed f32x2 FMA ----------------
// C[m][n] = sum_k A[m][k]*B[k][n]; A [NN x 128], B [128 x 128]
// ATT==0: A = (use_x ? x : g_H[l-1]), C = g_hW
// ATT==1: A = g_H[l]; score = sum_n tanh(C[m][n]) * avec[n] -> g_scores[:, l]
template<int ATT>
__global__ __launch_bounds__(256) void gemm_kernel(const float* __restrict__ x,
                                                   const float* __restrict__ B,
                                                   const float* __restrict__ avec,
                                                   int l, int use_x) {
    __shared__ float As[128][33];   // [m][k], pad 33
    __shared__ float Bs[32][128];   // [k][n]
    const float* A;
    if (ATT == 1)       A = g_H + (size_t)l * NN * CDIM;
    else if (use_x)     A = x;
    else                A = g_H + (size_t)(l - 1) * NN * CDIM;
    float* C = g_hW;

    int tid = threadIdx.x;
    int m0 = blockIdx.x * 128;
    int tx = tid & 15, ty = tid >> 4;

    // acc pairs along j: acc2[r][j2] = (acc[r][2*j2], acc[r][2*j2+1])
    ull acc2[8][4];
#pragma unroll
    for (int r = 0; r < 8; ++r)
#pragma unroll
        for (int j = 0; j < 4; ++j) acc2[r][j] = 0ull;

    for (int kc = 0; kc < 128; kc += 32) {
        __syncthreads();
#pragma unroll
        for (int it = 0; it < 4; ++it) {           // A chunk: 128 rows x 32 k
            int idx = it * 256 + tid;
            int m = idx >> 3, kq = idx & 7;
            int row = m0 + m;
            float4 v = make_float4(0.f, 0.f, 0.f, 0.f);
            if (row < NN) v = *(const float4*)(A + (size_t)row * 128 + kc + kq * 4);
            As[m][kq * 4 + 0] = v.x; As[m][kq * 4 + 1] = v.y;
            As[m][kq * 4 + 2] = v.z; As[m][kq * 4 + 3] = v.w;
        }
#pragma unroll
        for (int it = 0; it < 4; ++it) {           // B chunk: 32 k x 128 n
            int idx = it * 256 + tid;
            int k = idx >> 5, c = idx & 31;
            *(float4*)(&Bs[k][c * 4]) = *(const float4*)(B + (size_t)(kc + k) * 128 + c * 4);
        }
        __syncthreads();
#pragma unroll
        for (int kk = 0; kk < 32; ++kk) {
            float4 b0 = *(const float4*)(&Bs[kk][tx * 8]);
            float4 b1 = *(const float4*)(&Bs[kk][tx * 8 + 4]);
            ull b2[4];
            PACKF2(b2[0], b0.x, b0.y);   // adjacent regs from LDS.128 -> free pair
            PACKF2(b2[1], b0.z, b0.w);
            PACKF2(b2[2], b1.x, b1.y);
            PACKF2(b2[3], b1.z, b1.w);
#pragma unroll
            for (int r = 0; r < 8; ++r) {
                float ar = As[ty * 8 + r][kk];
                ull a2;
                PACKF2(a2, ar, ar);
#pragma unroll
                for (int j = 0; j < 4; ++j)
                    acc2[r][j] = ffma2(a2, b2[j], acc2[r][j]);
            }
        }
    }

    if (ATT == 0) {
#pragma unroll
        for (int r = 0; r < 8; ++r) {
            int row = m0 + ty * 8 + r;
            if (row < NN) {
                float o[8];
#pragma unroll
                for (int j = 0; j < 4; ++j) UNPACKF2(o[2 * j], o[2 * j + 1], acc2[r][j]);
                float4 o0 = make_float4(o[0], o[1], o[2], o[3]);
                float4 o1 = make_float4(o[4], o[5], o[6], o[7]);
                *(float4*)(C + (size_t)row * 128 + tx * 8)     = o0;
                *(float4*)(C + (size_t)row * 128 + tx * 8 + 4) = o1;
            }
        }
    } else {
        float aa[8];
#pragma unroll
        for (int j = 0; j < 8; ++j) aa[j] = avec[tx * 8 + j];
#pragma unroll
        for (int r = 0; r < 8; ++r) {
            float o[8];
#pragma unroll
            for (int j = 0; j < 4; ++j) UNPACKF2(o[2 * j], o[2 * j + 1], acc2[r][j]);
            float p = 0.f;
#pragma unroll
            for (int j = 0; j < 8; ++j) p += tanhf(o[j]) * aa[j];
            p += __shfl_xor_sync(0xffffffffu, p, 1);
            p += __shfl_xor_sync(0xffffffffu, p, 2);
            p += __shfl_xor_sync(0xffffffffu, p, 4);
            p += __shfl_xor_sync(0xffffffffu, p, 8);
            if (tx == 0) {
                int row = m0 + ty * 8 + r;
                if (row < NN) g_scores[(size_t)row * NLAYER + l] = p;
            }
        }
    }
}

// ---------------- aggregation: one warp per dst node ----------------
__global__ void agg_kernel(const float* __restrict__ convb, int l) {
    int w = (blockIdx.x * blockDim.x + threadIdx.x) >> 5;
    int lane = threadIdx.x & 31;
    if (w >= NN) return;
    const float* bias = convb + (size_t)l * CDIM;
    const float4* hw4 = (const float4*)g_hW;
    float4 acc = make_float4(0.f, 0.f, 0.f, 0.f);
    int e = g_rowptr[w], e1 = g_rowptr[w + 1];
    for (; e + 1 < e1; e += 2) {
        int s0 = g_col[e];     float w0 = g_ew[e];
        int s1 = g_col[e + 1]; float w1 = g_ew[e + 1];
        float4 v0 = hw4[(size_t)s0 * 32 + lane];
        float4 v1 = hw4[(size_t)s1 * 32 + lane];
        acc.x += w0 * v0.x + w1 * v1.x;
        acc.y += w0 * v0.y + w1 * v1.y;
        acc.z += w0 * v0.z + w1 * v1.z;
        acc.w += w0 * v0.w + w1 * v1.w;
    }
    if (e < e1) {
        int s0 = g_col[e]; float w0 = g_ew[e];
        float4 v0 = hw4[(size_t)s0 * 32 + lane];
        acc.x += w0 * v0.x; acc.y += w0 * v0.y;
        acc.z += w0 * v0.z; acc.w += w0 * v0.w;
    }
    float di = g_dinv[w];
    float sn = di * di;
    float4 sv = hw4[(size_t)w * 32 + lane];
    float4 b  = ((const float4*)bias)[lane];
    float4 r;
    r.x = fmaxf(acc.x + sn * sv.x + b.x, 0.f);
    r.y = fmaxf(acc.y + sn * sv.y + b.y, 0.f);
    r.z = fmaxf(acc.z + sn * sv.z + b.z, 0.f);
    r.w = fmaxf(acc.w + sn * sv.w + b.w, 0.f);
    ((float4*)(g_H + (size_t)l * NN * CDIM))[(size_t)w * 32 + lane] = r;
}

// ---------------- final: softmax over layers + layer-mix + out GEMM ----------------
__global__ __launch_bounds__(256) void final_kernel(const float* __restrict__ Wout,
                                                    const float* __restrict__ bout,
                                                    float* __restrict__ out) {
    __shared__ float At[128][33];
    __shared__ float Ws[128][40];
    __shared__ float sal[128][4];
    int tid = threadIdx.x;
    int m0 = blockIdx.x * 128;

    if (tid < 128) {
        int row = m0 + tid;
        float s0 = 0.f, s1 = 0.f, s2 = 0.f, s3 = 0.f;
        if (row < NN) {
            s0 = g_scores[(size_t)row * 4 + 0];
            s1 = g_scores[(size_t)row * 4 + 1];
            s2 = g_scores[(size_t)row * 4 + 2];
            s3 = g_scores[(size_t)row * 4 + 3];
        }
        float mx = fmaxf(fmaxf(s0, s1), fmaxf(s2, s3));
        float e0 = expf(s0 - mx), e1 = expf(s1 - mx), e2 = expf(s2 - mx), e3 = expf(s3 - mx);
        float inv = 1.0f / (e0 + e1 + e2 + e3);
        sal[tid][0] = e0 * inv; sal[tid][1] = e1 * inv;
        sal[tid][2] = e2 * inv; sal[tid][3] = e3 * inv;
    }
    for (int i = tid; i < 128 * 40; i += 256) Ws[i / 40][i % 40] = Wout[i];
    __syncthreads();

    float acc[4][5];
#pragma unroll
    for (int r = 0; r < 4; ++r)
#pragma unroll
        for (int j = 0; j < 5; ++j) acc[r][j] = 0.f;

    int ty = tid >> 3, tx = tid & 7;
    const size_t LSTR = (size_t)NN * CDIM;

    for (int kc = 0; kc < 128; kc += 32) {
#pragma unroll
        for (int it = 0; it < 4; ++it) {
            int idx = it * 256 + tid;
            int m = idx >> 3, kq = idx & 7;
            int row = m0 + m;
            float4 v = make_float4(0.f, 0.f, 0.f, 0.f);
            if (row < NN) {
                size_t off = (size_t)row * 128 + kc + kq * 4;
                float a0 = sal[m][0], a1 = sal[m][1], a2 = sal[m][2], a3 = sal[m][3];
                float4 h0 = *(const float4*)(g_H + off);
                float4 h1 = *(const float4*)(g_H + off + LSTR);
                float4 h2 = *(const float4*)(g_H + off + 2 * LSTR);
                float4 h3 = *(const float4*)(g_H + off + 3 * LSTR);
                v.x = a0 * h0.x + a1 * h1.x + a2 * h2.x + a3 * h3.x;
                v.y = a0 * h0.y + a1 * h1.y + a2 * h2.y + a3 * h3.y;
                v.z = a0 * h0.z + a1 * h1.z + a2 * h2.z + a3 * h3.z;
                v.w = a0 * h0.w + a1 * h1.w + a2 * h2.w + a3 * h3.w;
            }
            At[m][kq * 4 + 0] = v.x; At[m][kq * 4 + 1] = v.y;
            At[m][kq * 4 + 2] = v.z; At[m][kq * 4 + 3] = v.w;
        }
        __syncthreads();
#pragma unroll
        for (int kk = 0; kk < 32; ++kk) {
            float a[4];
#pragma unroll
            for (int r = 0; r < 4; ++r) a[r] = At[ty * 4 + r][kk];
            float b[5];
#pragma unroll
            for (int j = 0; j < 5; ++j) b[j] = Ws[kc + kk][tx * 5 + j];
#pragma unroll
            for (int r = 0; r < 4; ++r)
#pragma unroll
                for (int j = 0; j < 5; ++j) acc[r][j] += a[r] * b[j];
        }
        __syncthreads();
    }

#pragma unroll
    for (int r = 0; r < 4; ++r) {
        int row = m0 + ty * 4 + r;
        if (row < NN) {
#pragma unroll
            for (int j = 0; j < 5; ++j) {
                int col = tx * 5 + j;
                out[(size_t)row * NCLASS + col] = acc[r][j] + bout[col];
            }
        }
    }
}

// ---------------- launch ----------------
static const void* find_by_size(void* const* d_in, const int* in_sizes, int n_in,
                                long long want, const void* fallback) {
    for (int i = 0; i < n_in; ++i)
        if ((long long)in_sizes[i] == want) return d_in[i];
    return fallback;
}

extern "C" void kernel_launch(void* const* d_in, const int* in_sizes, int n_in,
                              void* d_out, int out_size) {
    const float* x     = (const float*)find_by_size(d_in, in_sizes, n_in, (long long)NN * CDIM, d_in[0]);
    const void*  ei    =               find_by_size(d_in, in_sizes, n_in, 2LL * NE,            d_in[1]);
    const float* convW = (const float*)find_by_size(d_in, in_sizes, n_in, (long long)NLAYER * CDIM * CDIM, d_in[2]);
    const float* convb = (const float*)find_by_size(d_in, in_sizes, n_in, (long long)NLAYER * CDIM, d_in[3]);
    const float* W_att = (const float*)find_by_size(d_in, in_sizes, n_in, (long long)CDIM * CDIM, d_in[4]);
    const float* a_att = (const float*)find_by_size(d_in, in_sizes, n_in, (long long)CDIM, d_in[5]);
    const float* W_out = (const float*)find_by_size(d_in, in_sizes, n_in, (long long)CDIM * NCLASS, d_in[6]);
    const float* b_out = (const float*)find_by_size(d_in, in_sizes, n_in, (long long)NCLASS, d_in[7]);
    float*       out   = (float*)d_out;

    detect_kernel<<<1, 1>>>(ei);
    zero_kernel<<<(NN + 255) / 256, 256>>>();
    hist_kernel<<<(NE + 255) / 256, 256>>>(ei);
    scan_dinv_kernel<<<1, 1024>>>();
    scatter_kernel<<<(NE + 255) / 256, 256>>>(ei);

    const int GB = (NN + 127) / 128;  // 391
    for (int l = 0; l < NLAYER; ++l) {
        gemm_kernel<0><<<GB, 256>>>(x, convW + (size_t)l * 128 * 128, nullptr, l, l == 0 ? 1 : 0);
        agg_kernel<<<(NN * 32 + 255) / 256, 256>>>(convb, l);
        gemm_kernel<1><<<GB, 256>>>(nullptr, W_att, a_att, l, 0);
    }
    final_kernel<<<GB, 256>>>(W_out, b_out, out);
}

// round 5
// speedup vs baseline: 1.3986x; 1.3986x over previous
#include <cuda_runtime.h>
#include <cuda_bf16.h>
#include <math.h>

#define NN 50000
#define NE 800000
#define CDIM 128
#define NLAYER 4
#define NCLASS 40

// ---------------- scratch (device globals; no allocation allowed) ----------------
__device__ int   g_is64;
__device__ int   g_deg[NN];
__device__ int   g_fill[NN];
__device__ int   g_rowptr[NN + 1];
__device__ float g_dinv[NN];
__device__ int   g_bsum[64];
__device__ int   g_boff[64];
__device__ int   g_col[NE];
__device__ __align__(16) float g_ew[NE];
__device__ __align__(16) float g_hW[(size_t)NN * CDIM];
__device__ __align__(16) float g_H[(size_t)NLAYER * NN * CDIM];
__device__ __align__(16) float g_scores[(size_t)NN * NLAYER];
// pre-split B weights, [n][k] layout, u32 = bf16x2 along k (64 u32 per row)
__device__ __align__(16) unsigned g_Bh[128 * 64];
__device__ __align__(16) unsigned g_Bl[128 * 64];
__device__ __align__(16) unsigned g_BhA[128 * 64];
__device__ __align__(16) unsigned g_BlA[128 * 64];

// ---------------- bf16 split helpers ----------------
__device__ __forceinline__ unsigned short bf_hi(float x) {
    return __bfloat16_as_ushort(__float2bfloat16(x));
}
__device__ __forceinline__ void split2(float x0, float x1, unsigned& hi, unsigned& lo) {
    unsigned short h0 = bf_hi(x0), h1 = bf_hi(x1);
    float r0 = x0 - __bfloat162float(__ushort_as_bfloat16(h0));
    float r1 = x1 - __bfloat162float(__ushort_as_bfloat16(h1));
    unsigned short l0 = bf_hi(r0), l1 = bf_hi(r1);
    hi = ((unsigned)h1 << 16) | h0;
    lo = ((unsigned)l1 << 16) | l0;
}

__device__ __forceinline__ void mma16816(float& c0, float& c1, float& c2, float& c3,
                                         unsigned a0, unsigned a1, unsigned a2, unsigned a3,
                                         unsigned b0, unsigned b1) {
    asm volatile("mma.sync.aligned.m16n8k16.row.col.f32.bf16.bf16.f32 "
                 "{%0,%1,%2,%3}, {%4,%5,%6,%7}, {%8,%9}, {%0,%1,%2,%3};"
                 : "+f"(c0), "+f"(c1), "+f"(c2), "+f"(c3)
                 : "r"(a0), "r"(a1), "r"(a2), "r"(a3), "r"(b0), "r"(b1));
}

// ---------------- edge dtype detection ----------------
__global__ void detect_kernel(const void* ei) {
    const long long* p = (const long long*)ei;
    int ok = 1;
    for (int i = 0; i < 8; ++i) {
        long long v = p[i];
        if (v < 0 || v >= NN) ok = 0;
    }
    g_is64 = ok;
}
__device__ __forceinline__ int edge_src(const void* ei, int e) {
    return g_is64 ? (int)((const long long*)ei)[e] : ((const int*)ei)[e];
}
__device__ __forceinline__ int edge_dst(const void* ei, int e) {
    return g_is64 ? (int)((const long long*)ei)[NE + e] : ((const int*)ei)[NE + e];
}

// ---------------- CSR build ----------------
__global__ void zero_kernel() {
    int i = blockIdx.x * blockDim.x + threadIdx.x;
    if (i < NN) { g_deg[i] = 0; g_fill[i] = 0; }
}

__global__ void hist_kernel(const void* __restrict__ ei) {
    int e = blockIdx.x * blockDim.x + threadIdx.x;
    if (e < NE) {
        int d = edge_dst(ei, e);
        if ((unsigned)d < NN) atomicAdd(&g_deg[d], 1);
    }
}

// coalesced 3-phase scan
__global__ __launch_bounds__(1024) void scan1_kernel() {
    __shared__ int wsum[32];
    int b = blockIdx.x, t = threadIdx.x;
    int i = b * 1024 + t;
    int lane = t & 31, wid = t >> 5;
    int v = (i < NN) ? g_deg[i] : 0;
    if (i < NN) g_dinv[i] = rsqrtf(1.0f + (float)v);
    int inc = v;
#pragma unroll
    for (int o = 1; o < 32; o <<= 1) {
        int u = __shfl_up_sync(0xffffffffu, inc, o);
        if (lane >= o) inc += u;
    }
    if (lane == 31) wsum[wid] = inc;
    __syncthreads();
    if (wid == 0) {
        int s = wsum[lane];
#pragma unroll
        for (int o = 1; o < 32; o <<= 1) {
            int u = __shfl_up_sync(0xffffffffu, s, o);
            if (lane >= o) s += u;
        }
        wsum[lane] = s;
    }
    __syncthreads();
    int incl = inc + (wid ? wsum[wid - 1] : 0);
    if (i < NN) g_rowptr[i + 1] = incl;   // pre-offset
    if (t == 1023) g_bsum[b] = incl;
}

__global__ void scan2_kernel() {
    __shared__ int sm[64];
    int t = threadIdx.x;
    int v = (t < 49) ? g_bsum[t] : 0;
    sm[t] = v;
    __syncthreads();
    for (int o = 1; o < 64; o <<= 1) {
        int u = (t >= o) ? sm[t - o] : 0;
        __syncthreads();
        sm[t] += u;
        __syncthreads();
    }
    g_boff[t] = sm[t] - v;   // exclusive
}

__global__ __launch_bounds__(1024) void scan3_kernel() {
    int b = blockIdx.x, t = threadIdx.x;
    int i = b * 1024 + t;
    if (i < NN) g_rowptr[i + 1] += g_boff[b];
    if (i == 0) g_rowptr[0] = 0;
}

__global__ void scatter_kernel(const void* __restrict__ ei) {
    int e = blockIdx.x * blockDim.x + threadIdx.x;
    if (e < NE) {
        int s = edge_src(ei, e);
        int d = edge_dst(ei, e);
        if ((unsigned)s < NN && (unsigned)d < NN) {
            int pos = g_rowptr[d] + atomicAdd(&g_fill[d], 1);
            g_col[pos] = s;
            g_ew[pos]  = g_dinv[s] * g_dinv[d];
        }
    }
}

// ---------------- B prep: split fp32 [k][n] weight into bf16 hi/lo in [n][k] ----------------
__global__ void bprep_kernel(const float* __restrict__ B, int att) {
    int idx = blockIdx.x * 256 + threadIdx.x;
    if (idx >= 128 * 64) return;
    int n = idx >> 6, q = idx & 63, k = q * 2;
    float x0 = B[(size_t)k * 128 + n];
    float x1 = B[(size_t)(k + 1) * 128 + n];
    unsigned hi, lo;
    split2(x0, x1, hi, lo);
    unsigned* dh = att ? g_BhA : g_Bh;
    unsigned* dl = att ? g_BlA : g_Bl;
    dh[n * 64 + q] = hi;
    dl[n * 64 + q] = lo;
}

// ---------------- tensor-core GEMM (split bf16), 128x128 tile, 8 warps ----------------
// C[m][n] = sum_k A[m][k]*B[k][n]
// ATT==0: A = (use_x ? x : g_H[l-1]) -> C = g_hW
// ATT==1: A = g_H[l] -> scores via tanh/a_att
template<int ATT>
__global__ __launch_bounds__(256) void gemm_kernel(const float* __restrict__ x,
                                                   const float* __restrict__ avec,
                                                   int l, int use_x) {
    __shared__ unsigned short Ah[128][36], Al[128][36];  // [m][k], stride 72B
    __shared__ unsigned short Bh[128][36], Bl[128][36];  // [n][k]
    __shared__ float red[128][2];

    const float* A;
    if (ATT == 1)   A = g_H + (size_t)l * NN * CDIM;
    else if (use_x) A = x;
    else            A = g_H + (size_t)(l - 1) * NN * CDIM;
    const unsigned* GBh = ATT ? g_BhA : g_Bh;
    const unsigned* GBl = ATT ? g_BlA : g_Bl;

    int tid = threadIdx.x;
    int m0 = blockIdx.x * 128;
    int lane = tid & 31, w = tid >> 5;
    int g = lane >> 2, t = lane & 3;
    int wm = (w & 3) * 32;       // warp m offset (4 warps along m)
    int wn = (w >> 2) * 64;      // warp n offset (2 warps along n)

    float c[2][8][4];
#pragma unroll
    for (int s = 0; s < 2; ++s)
#pragma unroll
        for (int j = 0; j < 8; ++j)
#pragma unroll
            for (int q = 0; q < 4; ++q) c[s][j][q] = 0.f;

    for (int kc = 0; kc < 128; kc += 32) {
        __syncthreads();
        // stage A: 128 rows x 32 k fp32 -> split bf16
#pragma unroll
        for (int it = 0; it < 4; ++it) {
            int idx = it * 256 + tid;      // 1024 float4 loads
            int m = idx >> 3, q = idx & 7; // q: float4 within 32k
            int row = m0 + m;
            float4 v = make_float4(0.f, 0.f, 0.f, 0.f);
            if (row < NN) v = *(const float4*)(A + (size_t)row * 128 + kc + q * 4);
            unsigned h0, l0, h1, l1;
            split2(v.x, v.y, h0, l0);
            split2(v.z, v.w, h1, l1);
            *(unsigned*)&Ah[m][q * 4]     = h0;
            *(unsigned*)&Ah[m][q * 4 + 2] = h1;
            *(unsigned*)&Al[m][q * 4]     = l0;
            *(unsigned*)&Al[m][q * 4 + 2] = l1;
        }
        // stage B: copy pre-split bf16 [n][kc..kc+31]
#pragma unroll
        for (int it = 0; it < 16; ++it) {
            int idx = it * 256 + tid;          // 4096 u32 copies (hi+lo)
            int half = idx >> 11;              // 0: hi, 1: lo
            int r = idx & 2047;
            int n = r >> 4, q = r & 15;        // q: u32 within 32k (k = 2q)
            unsigned val = (half ? GBl : GBh)[n * 64 + (kc >> 1) + q];
            if (half) *(unsigned*)&Bl[n][q * 2] = val;
            else      *(unsigned*)&Bh[n][q * 2] = val;
        }
        __syncthreads();

#pragma unroll
        for (int ks = 0; ks < 32; ks += 16) {
            // A fragments for the 2 sub-tiles (hi and lo)
            unsigned ah[2][4], al[2][4];
#pragma unroll
            for (int s = 0; s < 2; ++s) {
                int rb = wm + s * 16 + g;
                ah[s][0] = *(unsigned*)&Ah[rb][ks + 2 * t];
                ah[s][1] = *(unsigned*)&Ah[rb + 8][ks + 2 * t];
                ah[s][2] = *(unsigned*)&Ah[rb][ks + 2 * t + 8];
                ah[s][3] = *(unsigned*)&Ah[rb + 8][ks + 2 * t + 8];
                al[s][0] = *(unsigned*)&Al[rb][ks + 2 * t];
                al[s][1] = *(unsigned*)&Al[rb + 8][ks + 2 * t];
                al[s][2] = *(unsigned*)&Al[rb][ks + 2 * t + 8];
                al[s][3] = *(unsigned*)&Al[rb + 8][ks + 2 * t + 8];
            }
#pragma unroll
            for (int j = 0; j < 8; ++j) {
                int nb = wn + j * 8 + g;
                unsigned bh0 = *(unsigned*)&Bh[nb][ks + 2 * t];
                unsigned bh1 = *(unsigned*)&Bh[nb][ks + 2 * t + 8];
                unsigned bl0 = *(unsigned*)&Bl[nb][ks + 2 * t];
                unsigned bl1 = *(unsigned*)&Bl[nb][ks + 2 * t + 8];
#pragma unroll
                for (int s = 0; s < 2; ++s) {
                    mma16816(c[s][j][0], c[s][j][1], c[s][j][2], c[s][j][3],
                             ah[s][0], ah[s][1], ah[s][2], ah[s][3], bh0, bh1);
                    mma16816(c[s][j][0], c[s][j][1], c[s][j][2], c[s][j][3],
                             ah[s][0], ah[s][1], ah[s][2], ah[s][3], bl0, bl1);
                    mma16816(c[s][j][0], c[s][j][1], c[s][j][2], c[s][j][3],
                             al[s][0], al[s][1], al[s][2], al[s][3], bh0, bh1);
                }
            }
        }
    }

    if (ATT == 0) {
        float* C = g_hW;
#pragma unroll
        for (int s = 0; s < 2; ++s) {
#pragma unroll
            for (int j = 0; j < 8; ++j) {
                int r = m0 + wm + s * 16 + g;
                int n = wn + j * 8 + 2 * t;
                if (r < NN)     *(float2*)(C + (size_t)r * 128 + n)       = make_float2(c[s][j][0], c[s][j][1]);
                if (r + 8 < NN) *(float2*)(C + (size_t)(r + 8) * 128 + n) = make_float2(c[s][j][2], c[s][j][3]);
            }
        }
    } else {
        // per-thread partials for rows (wm+s*16+g) and (+8)
        float p[2][2] = {{0.f, 0.f}, {0.f, 0.f}};
#pragma unroll
        for (int j = 0; j < 8; ++j) {
            int n = wn + j * 8 + 2 * t;
            float a0 = avec[n], a1 = avec[n + 1];
#pragma unroll
            for (int s = 0; s < 2; ++s) {
                p[s][0] += tanhf(c[s][j][0]) * a0 + tanhf(c[s][j][1]) * a1;
                p[s][1] += tanhf(c[s][j][2]) * a0 + tanhf(c[s][j][3]) * a1;
            }
        }
        // reduce over t (lanes within quad)
#pragma unroll
        for (int s = 0; s < 2; ++s)
#pragma unroll
            for (int h = 0; h < 2; ++h) {
                p[s][h] += __shfl_xor_sync(0xffffffffu, p[s][h], 1);
                p[s][h] += __shfl_xor_sync(0xffffffffu, p[s][h], 2);
            }
        __syncthreads();
        if (t == 0) {
#pragma unroll
            for (int s = 0; s < 2; ++s) {
                red[wm + s * 16 + g][w >> 2]     = p[s][0];
                red[wm + s * 16 + g + 8][w >> 2] = p[s][1];
            }
        }
        __syncthreads();
        if (tid < 128) {
            int row = m0 + tid;
            if (row < NN)
                g_scores[(size_t)row * NLAYER + l] = red[tid][0] + red[tid][1];
        }
    }
}

// ---------------- aggregation: one warp per dst node ----------------
__global__ void agg_kernel(const float* __restrict__ convb, int l) {
    int w = (blockIdx.x * blockDim.x + threadIdx.x) >> 5;
    int lane = threadIdx.x & 31;
    if (w >= NN) return;
    const float* bias = convb + (size_t)l * CDIM;
    const float4* hw4 = (const float4*)g_hW;
    float4 acc = make_float4(0.f, 0.f, 0.f, 0.f);
    int e = g_rowptr[w], e1 = g_rowptr[w + 1];
    for (; e + 1 < e1; e += 2) {
        int s0 = g_col[e];     float w0 = g_ew[e];
        int s1 = g_col[e + 1]; float w1 = g_ew[e + 1];
        float4 v0 = hw4[(size_t)s0 * 32 + lane];
        float4 v1 = hw4[(size_t)s1 * 32 + lane];
        acc.x += w0 * v0.x + w1 * v1.x;
        acc.y += w0 * v0.y + w1 * v1.y;
        acc.z += w0 * v0.z + w1 * v1.z;
        acc.w += w0 * v0.w + w1 * v1.w;
    }
    if (e < e1) {
        int s0 = g_col[e]; float w0 = g_ew[e];
        float4 v0 = hw4[(size_t)s0 * 32 + lane];
        acc.x += w0 * v0.x; acc.y += w0 * v0.y;
        acc.z += w0 * v0.z; acc.w += w0 * v0.w;
    }
    float di = g_dinv[w];
    float sn = di * di;
    float4 sv = hw4[(size_t)w * 32 + lane];
    float4 b  = ((const float4*)bias)[lane];
    float4 r;
    r.x = fmaxf(acc.x + sn * sv.x + b.x, 0.f);
    r.y = fmaxf(acc.y + sn * sv.y + b.y, 0.f);
    r.z = fmaxf(acc.z + sn * sv.z + b.z, 0.f);
    r.w = fmaxf(acc.w + sn * sv.w + b.w, 0.f);
    ((float4*)(g_H + (size_t)l * NN * CDIM))[(size_t)w * 32 + lane] = r;
}

// ---------------- final: softmax over layers + layer-mix + out GEMM ----------------
__global__ __launch_bounds__(256) void final_kernel(const float* __restrict__ Wout,
                                                    const float* __restrict__ bout,
                                                    float* __restrict__ out) {
    __shared__ float At[128][33];
    __shared__ float Ws[128][40];
    __shared__ float sal[128][4];
    int tid = threadIdx.x;
    int m0 = blockIdx.x * 128;

    if (tid < 128) {
        int row = m0 + tid;
        float s0 = 0.f, s1 = 0.f, s2 = 0.f, s3 = 0.f;
        if (row < NN) {
            s0 = g_scores[(size_t)row * 4 + 0];
            s1 = g_scores[(size_t)row * 4 + 1];
            s2 = g_scores[(size_t)row * 4 + 2];
            s3 = g_scores[(size_t)row * 4 + 3];
        }
        float mx = fmaxf(fmaxf(s0, s1), fmaxf(s2, s3));
        float e0 = expf(s0 - mx), e1 = expf(s1 - mx), e2 = expf(s2 - mx), e3 = expf(s3 - mx);
        float inv = 1.0f / (e0 + e1 + e2 + e3);
        sal[tid][0] = e0 * inv; sal[tid][1] = e1 * inv;
        sal[tid][2] = e2 * inv; sal[tid][3] = e3 * inv;
    }
    for (int i = tid; i < 128 * 40; i += 256) Ws[i / 40][i % 40] = Wout[i];
    __syncthreads();

    float acc[4][5];
#pragma unroll
    for (int r = 0; r < 4; ++r)
#pragma unroll
        for (int j = 0; j < 5; ++j) acc[r][j] = 0.f;

    int ty = tid >> 3, tx = tid & 7;
    const size_t LSTR = (size_t)NN * CDIM;

    for (int kc = 0; kc < 128; kc += 32) {
#pragma unroll
        for (int it = 0; it < 4; ++it) {
            int idx = it * 256 + tid;
            int m = idx >> 3, kq = idx & 7;
            int row = m0 + m;
            float4 v = make_float4(0.f, 0.f, 0.f, 0.f);
            if (row < NN) {
                size_t off = (size_t)row * 128 + kc + kq * 4;
                float a0 = sal[m][0], a1 = sal[m][1], a2 = sal[m][2], a3 = sal[m][3];
                float4 h0 = *(const float4*)(g_H + off);
                float4 h1 = *(const float4*)(g_H + off + LSTR);
                float4 h2 = *(const float4*)(g_H + off + 2 * LSTR);
                float4 h3 = *(const float4*)(g_H + off + 3 * LSTR);
                v.x = a0 * h0.x + a1 * h1.x + a2 * h2.x + a3 * h3.x;
                v.y = a0 * h0.y + a1 * h1.y + a2 * h2.y + a3 * h3.y;
                v.z = a0 * h0.z + a1 * h1.z + a2 * h2.z + a3 * h3.z;
                v.w = a0 * h0.w + a1 * h1.w + a2 * h2.w + a3 * h3.w;
            }
            At[m][kq * 4 + 0] = v.x; At[m][kq * 4 + 1] = v.y;
            At[m][kq * 4 + 2] = v.z; At[m][kq * 4 + 3] = v.w;
        }
        __syncthreads();
#pragma unroll
        for (int kk = 0; kk < 32; ++kk) {
            float a[4];
#pragma unroll
            for (int r = 0; r < 4; ++r) a[r] = At[ty * 4 + r][kk];
            float b[5];
#pragma unroll
            for (int j = 0; j < 5; ++j) b[j] = Ws[kc + kk][tx * 5 + j];
#pragma unroll
            for (int r = 0; r < 4; ++r)
#pragma unroll
                for (int j = 0; j < 5; ++j) acc[r][j] += a[r] * b[j];
        }
        __syncthreads();
    }

#pragma unroll
    for (int r = 0; r < 4; ++r) {
        int row = m0 + ty * 4 + r;
        if (row < NN) {
#pragma unroll
            for (int j = 0; j < 5; ++j) {
                int col = tx * 5 + j;
                out[(size_t)row * NCLASS + col] = acc[r][j] + bout[col];
            }
        }
    }
}

// ---------------- launch ----------------
static const void* find_by_size(void* const* d_in, const int* in_sizes, int n_in,
                                long long want, const void* fallback) {
    for (int i = 0; i < n_in; ++i)
        if ((long long)in_sizes[i] == want) return d_in[i];
    return fallback;
}

extern "C" void kernel_launch(void* const* d_in, const int* in_sizes, int n_in,
                              void* d_out, int out_size) {
    const float* x     = (const float*)find_by_size(d_in, in_sizes, n_in, (long long)NN * CDIM, d_in[0]);
    const void*  ei    =               find_by_size(d_in, in_sizes, n_in, 2LL * NE,            d_in[1]);
    const float* convW = (const float*)find_by_size(d_in, in_sizes, n_in, (long long)NLAYER * CDIM * CDIM, d_in[2]);
    const float* convb = (const float*)find_by_size(d_in, in_sizes, n_in, (long long)NLAYER * CDIM, d_in[3]);
    const float* W_att = (const float*)find_by_size(d_in, in_sizes, n_in, (long long)CDIM * CDIM, d_in[4]);
    const float* a_att = (const float*)find_by_size(d_in, in_sizes, n_in, (long long)CDIM, d_in[5]);
    const float* W_out = (const float*)find_by_size(d_in, in_sizes, n_in, (long long)CDIM * NCLASS, d_in[6]);
    const float* b_out = (const float*)find_by_size(d_in, in_sizes, n_in, (long long)NCLASS, d_in[7]);
    float*       out   = (float*)d_out;

    detect_kernel<<<1, 1>>>(ei);
    zero_kernel<<<(NN + 255) / 256, 256>>>();
    hist_kernel<<<(NE + 255) / 256, 256>>>(ei);
    scan1_kernel<<<49, 1024>>>();
    scan2_kernel<<<1, 64>>>();
    scan3_kernel<<<49, 1024>>>();
    scatter_kernel<<<(NE + 255) / 256, 256>>>(ei);
    bprep_kernel<<<32, 256>>>(W_att, 1);   // attention weight, prepped once

    const int GB = (NN + 127) / 128;  // 391
    for (int l = 0; l < NLAYER; ++l) {
        bprep_kernel<<<32, 256>>>(convW + (size_t)l * 128 * 128, 0);
        gemm_kernel<0><<<GB, 256>>>(x, nullptr, l, l == 0 ? 1 : 0);
        agg_kernel<<<(NN * 32 + 255) / 256, 256>>>(convb, l);
        gemm_kernel<1><<<GB, 256>>>(nullptr, a_att, l, 0);
    }
    final_kernel<<<GB, 256>>>(W_out, b_out, out);
}

// round 7
// speedup vs baseline: 1.7351x; 1.2406x over previous
#include <cuda_runtime.h>
#include <cuda_bf16.h>
#include <math.h>

#define NN 50000
#define NE 800000
#define CDIM 128
#define NLAYER 4
#define NCLASS 40

// ---------------- scratch (device globals; no allocation allowed) ----------------
__device__ int   g_is64;
__device__ int   g_deg[NN];
__device__ int   g_fill[NN];
__device__ int   g_rowptr[NN + 1];
__device__ float g_dinv[NN];
__device__ int   g_bsum[64];
__device__ int   g_boff[64];
__device__ int   g_col[NE];
__device__ __align__(16) float g_ew[NE];
__device__ __align__(16) float g_hW[(size_t)NN * CDIM];
__device__ __align__(16) float g_H[(size_t)NLAYER * NN * CDIM];
__device__ __align__(16) float g_scores[(size_t)NN * NLAYER];
// pre-split weights: slot 0..3 = convW layers, slot 4 = W_att; [n][k] bf16x2 u32
__device__ __align__(16) unsigned g_Bh[5 * 128 * 64];
__device__ __align__(16) unsigned g_Bl[5 * 128 * 64];

// ---------------- helpers ----------------
__device__ __forceinline__ unsigned short bf_hi(float x) {
    return __bfloat16_as_ushort(__float2bfloat16(x));
}
__device__ __forceinline__ void split2(float x0, float x1, unsigned& hi, unsigned& lo) {
    unsigned short h0 = bf_hi(x0), h1 = bf_hi(x1);
    float r0 = x0 - __bfloat162float(__ushort_as_bfloat16(h0));
    float r1 = x1 - __bfloat162float(__ushort_as_bfloat16(h1));
    unsigned short l0 = bf_hi(r0), l1 = bf_hi(r1);
    hi = ((unsigned)h1 << 16) | h0;
    lo = ((unsigned)l1 << 16) | l0;
}
__device__ __forceinline__ void mma16816(float& c0, float& c1, float& c2, float& c3,
                                         unsigned a0, unsigned a1, unsigned a2, unsigned a3,
                                         unsigned b0, unsigned b1) {
    asm volatile("mma.sync.aligned.m16n8k16.row.col.f32.bf16.bf16.f32 "
                 "{%0,%1,%2,%3}, {%4,%5,%6,%7}, {%8,%9}, {%0,%1,%2,%3};"
                 : "+f"(c0), "+f"(c1), "+f"(c2), "+f"(c3)
                 : "r"(a0), "r"(a1), "r"(a2), "r"(a3), "r"(b0), "r"(b1));
}
__device__ __forceinline__ unsigned smem_u32(const void* p) {
    unsigned a;
    asm("{ .reg .u64 t; cvta.to.shared.u64 t, %1; cvt.u32.u64 %0, t; }" : "=r"(a) : "l"(p));
    return a;
}
__device__ __forceinline__ void ldsm_x4(unsigned& r0, unsigned& r1, unsigned& r2, unsigned& r3,
                                        unsigned addr) {
    asm volatile("ldmatrix.sync.aligned.m8n8.x4.shared.b16 {%0,%1,%2,%3}, [%4];"
                 : "=r"(r0), "=r"(r1), "=r"(r2), "=r"(r3) : "r"(addr));
}

// ---------------- edge dtype detection ----------------
__global__ void detect_kernel(const void* ei) {
    const long long* p = (const long long*)ei;
    int ok = 1;
    for (int i = 0; i < 8; ++i) {
        long long v = p[i];
        if (v < 0 || v >= NN) ok = 0;
    }
    g_is64 = ok;
}
__device__ __forceinline__ int edge_src(const void* ei, int e) {
    return g_is64 ? (int)((const long long*)ei)[e] : ((const int*)ei)[e];
}
__device__ __forceinline__ int edge_dst(const void* ei, int e) {
    return g_is64 ? (int)((const long long*)ei)[NE + e] : ((const int*)ei)[NE + e];
}

// ---------------- CSR build ----------------
__global__ void zero_kernel() {
    int i = blockIdx.x * blockDim.x + threadIdx.x;
    if (i < NN) { g_deg[i] = 0; g_fill[i] = 0; }
}
__global__ void hist_kernel(const void* __restrict__ ei) {
    int e = blockIdx.x * blockDim.x + threadIdx.x;
    if (e < NE) {
        int d = edge_dst(ei, e);
        if ((unsigned)d < NN) atomicAdd(&g_deg[d], 1);
    }
}
__global__ __launch_bounds__(1024) void scan1_kernel() {
    __shared__ int wsum[32];
    int b = blockIdx.x, t = threadIdx.x;
    int i = b * 1024 + t;
    int lane = t & 31, wid = t >> 5;
    int v = (i < NN) ? g_deg[i] : 0;
    if (i < NN) g_dinv[i] = rsqrtf(1.0f + (float)v);
    int inc = v;
#pragma unroll
    for (int o = 1; o < 32; o <<= 1) {
        int u = __shfl_up_sync(0xffffffffu, inc, o);
        if (lane >= o) inc += u;
    }
    if (lane == 31) wsum[wid] = inc;
    __syncthreads();
    if (wid == 0) {
        int s = wsum[lane];
#pragma unroll
        for (int o = 1; o < 32; o <<= 1) {
            int u = __shfl_up_sync(0xffffffffu, s, o);
            if (lane >= o) s += u;
        }
        wsum[lane] = s;
    }
    __syncthreads();
    int incl = inc + (wid ? wsum[wid - 1] : 0);
    if (i < NN) g_rowptr[i + 1] = incl;
    if (t == 1023) g_bsum[b] = incl;
}
__global__ void scan2_kernel() {
    __shared__ int sm[64];
    int t = threadIdx.x;
    int v = (t < 49) ? g_bsum[t] : 0;
    sm[t] = v;
    __syncthreads();
    for (int o = 1; o < 64; o <<= 1) {
        int u = (t >= o) ? sm[t - o] : 0;
        __syncthreads();
        sm[t] += u;
        __syncthreads();
    }
    g_boff[t] = sm[t] - v;
}
__global__ __launch_bounds__(1024) void scan3_kernel() {
    int b = blockIdx.x, t = threadIdx.x;
    int i = b * 1024 + t;
    if (i < NN) g_rowptr[i + 1] += g_boff[b];
    if (i == 0) g_rowptr[0] = 0;
}
__global__ void scatter_kernel(const void* __restrict__ ei) {
    int e = blockIdx.x * blockDim.x + threadIdx.x;
    if (e < NE) {
        int s = edge_src(ei, e);
        int d = edge_dst(ei, e);
        if ((unsigned)s < NN && (unsigned)d < NN) {
            int pos = g_rowptr[d] + atomicAdd(&g_fill[d], 1);
            g_col[pos] = s;
            g_ew[pos]  = g_dinv[s] * g_dinv[d];
        }
    }
}

// ---------------- B prep: all 5 weight matrices at once ----------------
__global__ void bprep_kernel(const float* __restrict__ convW, const float* __restrict__ Watt) {
    int idx = blockIdx.x * 256 + threadIdx.x;
    if (idx >= 5 * 128 * 64) return;
    int slot = idx >> 13;          // 0..4
    int r = idx & 8191;
    int n = r >> 6, q = r & 63, k = q * 2;
    const float* B = (slot < 4) ? (convW + (size_t)slot * 128 * 128) : Watt;
    float x0 = B[(size_t)k * 128 + n];
    float x1 = B[(size_t)(k + 1) * 128 + n];
    unsigned hi, lo;
    split2(x0, x1, hi, lo);
    g_Bh[slot * 8192 + n * 64 + q] = hi;
    g_Bl[slot * 8192 + n * 64 + q] = lo;
}

// ---------------- tensor-core GEMM (split bf16) ----------------
// ATT==0: A = (use_x ? x : g_H[l-1]) [NN x 128], B = convW[l] -> C = g_hW
// ATT==1: A = g_H (batched, 4*NN rows), B = W_att -> scores (all layers)
template<int ATT>
__global__ __launch_bounds__(256, 2) void gemm_kernel(const float* __restrict__ x,
                                                      const float* __restrict__ avec,
                                                      int l, int use_x) {
    __shared__ unsigned short Ah[128][40], Al[128][40];   // row stride 80B = 16*5
    __shared__ unsigned short Bh[128][40], Bl[128][40];
    __shared__ float red[128][2];

    const float* A;
    int Mrows;
    if (ATT) { A = g_H; Mrows = NLAYER * NN; }
    else     { A = use_x ? x : (g_H + (size_t)(l - 1) * NN * CDIM); Mrows = NN; }
    const unsigned* GBh = g_Bh + (ATT ? 4 : l) * 8192;
    const unsigned* GBl = g_Bl + (ATT ? 4 : l) * 8192;

    int tid = threadIdx.x;
    int m0 = blockIdx.x * 128;
    int lane = tid & 31, w = tid >> 5;
    int g = lane >> 2, t = lane & 3;
    int wm = (w & 3) * 32, wn = (w >> 2) * 64;

    // staging indices
    int sa_m = tid >> 1;                 // unused pattern placeholder (see loop)
    (void)sa_m;

    // ldmatrix lane-address bases (byte cols added per ks)
    int mi = lane >> 3, r8 = lane & 7;
    unsigned a_h[2], a_l[2];
#pragma unroll
    for (int s = 0; s < 2; ++s) {
        int row = wm + s * 16 + (mi & 1) * 8 + r8;
        int col = (mi >> 1) * 8;
        a_h[s] = smem_u32(&Ah[row][col]);
        a_l[s] = smem_u32(&Al[row][col]);
    }
    unsigned b_h[4], b_l[4];
#pragma unroll
    for (int jp = 0; jp < 4; ++jp) {
        int row = wn + jp * 16 + (mi >> 1) * 8 + r8;   // matrices 0,1: tile j; 2,3: tile j+1
        int col = (mi & 1) * 8;
        b_h[jp] = smem_u32(&Bh[row][col]);
        b_l[jp] = smem_u32(&Bl[row][col]);
    }

    float c[2][8][4];
#pragma unroll
    for (int s = 0; s < 2; ++s)
#pragma unroll
        for (int j = 0; j < 8; ++j)
#pragma unroll
            for (int q = 0; q < 4; ++q) c[s][j][q] = 0.f;

    // prefetch chunk 0 A into regs
    float4 pf[4];
#pragma unroll
    for (int it = 0; it < 4; ++it) {
        int idx = it * 256 + tid;
        int m = idx >> 3, q = idx & 7;
        int row = m0 + m;
        pf[it] = make_float4(0.f, 0.f, 0.f, 0.f);
        if (row < Mrows) pf[it] = *(const float4*)(A + (size_t)row * 128 + q * 4);
    }

    for (int kc = 0; kc < 128; kc += 32) {
        // store prefetched A (split)
#pragma unroll
        for (int it = 0; it < 4; ++it) {
            int idx = it * 256 + tid;
            int m = idx >> 3, q = idx & 7;
            unsigned h0, l0, h1, l1;
            split2(pf[it].x, pf[it].y, h0, l0);
            split2(pf[it].z, pf[it].w, h1, l1);
            *(unsigned*)&Ah[m][q * 4]     = h0;
            *(unsigned*)&Ah[m][q * 4 + 2] = h1;
            *(unsigned*)&Al[m][q * 4]     = l0;
            *(unsigned*)&Al[m][q * 4 + 2] = l1;
        }
        // stage B chunk
#pragma unroll
        for (int it = 0; it < 16; ++it) {
            int idx = it * 256 + tid;
            int half = idx >> 11;
            int rr = idx & 2047;
            int n = rr >> 4, q = rr & 15;
            unsigned val = (half ? GBl : GBh)[n * 64 + (kc >> 1) + q];
            if (half) *(unsigned*)&Bl[n][q * 2] = val;
            else      *(unsigned*)&Bh[n][q * 2] = val;
        }
        __syncthreads();

        // prefetch next chunk A (overlaps with mma below)
        if (kc < 96) {
#pragma unroll
            for (int it = 0; it < 4; ++it) {
                int idx = it * 256 + tid;
                int m = idx >> 3, q = idx & 7;
                int row = m0 + m;
                pf[it] = make_float4(0.f, 0.f, 0.f, 0.f);
                if (row < Mrows) pf[it] = *(const float4*)(A + (size_t)row * 128 + kc + 32 + q * 4);
            }
        }

#pragma unroll
        for (int ks = 0; ks < 32; ks += 16) {
            unsigned koff = ks * 2;   // bytes
            unsigned ah[2][4], al[2][4];
#pragma unroll
            for (int s = 0; s < 2; ++s) {
                ldsm_x4(ah[s][0], ah[s][1], ah[s][2], ah[s][3], a_h[s] + koff);
                ldsm_x4(al[s][0], al[s][1], al[s][2], al[s][3], a_l[s] + koff);
            }
#pragma unroll
            for (int jp = 0; jp < 4; ++jp) {
                unsigned bh0, bh1, bh2, bh3, bl0, bl1, bl2, bl3;
                ldsm_x4(bh0, bh1, bh2, bh3, b_h[jp] + koff);
                ldsm_x4(bl0, bl1, bl2, bl3, b_l[jp] + koff);
#pragma unroll
                for (int s = 0; s < 2; ++s) {
                    mma16816(c[s][2 * jp][0], c[s][2 * jp][1], c[s][2 * jp][2], c[s][2 * jp][3],
                             ah[s][0], ah[s][1], ah[s][2], ah[s][3], bh0, bh1);
                    mma16816(c[s][2 * jp][0], c[s][2 * jp][1], c[s][2 * jp][2], c[s][2 * jp][3],
                             ah[s][0], ah[s][1], ah[s][2], ah[s][3], bl0, bl1);
                    mma16816(c[s][2 * jp][0], c[s][2 * jp][1], c[s][2 * jp][2], c[s][2 * jp][3],
                             al[s][0], al[s][1], al[s][2], al[s][3], bh0, bh1);
                    mma16816(c[s][2 * jp + 1][0], c[s][2 * jp + 1][1], c[s][2 * jp + 1][2], c[s][2 * jp + 1][3],
                             ah[s][0], ah[s][1], ah[s][2], ah[s][3], bh2, bh3);
                    mma16816(c[s][2 * jp + 1][0], c[s][2 * jp + 1][1], c[s][2 * jp + 1][2], c[s][2 * jp + 1][3],
                             ah[s][0], ah[s][1], ah[s][2], ah[s][3], bl2, bl3);
                    mma16816(c[s][2 * jp + 1][0], c[s][2 * jp + 1][1], c[s][2 * jp + 1][2], c[s][2 * jp + 1][3],
                             al[s][0], al[s][1], al[s][2], al[s][3], bh2, bh3);
                }
            }
        }
        __syncthreads();
    }

    if (ATT == 0) {
        float* C = g_hW;
#pragma unroll
        for (int s = 0; s < 2; ++s) {
#pragma unroll
            for (int j = 0; j < 8; ++j) {
                int rr = m0 + wm + s * 16 + g;
                int n = wn + j * 8 + 2 * t;
                if (rr < NN)     *(float2*)(C + (size_t)rr * 128 + n)       = make_float2(c[s][j][0], c[s][j][1]);
                if (rr + 8 < NN) *(float2*)(C + (size_t)(rr + 8) * 128 + n) = make_float2(c[s][j][2], c[s][j][3]);
            }
        }
    } else {
        float p[2][2] = {{0.f, 0.f}, {0.f, 0.f}};
#pragma unroll
        for (int j = 0; j < 8; ++j) {
            int n = wn + j * 8 + 2 * t;
            float a0 = avec[n], a1 = avec[n + 1];
#pragma unroll
            for (int s = 0; s < 2; ++s) {
                p[s][0] += tanhf(c[s][j][0]) * a0 + tanhf(c[s][j][1]) * a1;
                p[s][1] += tanhf(c[s][j][2]) * a0 + tanhf(c[s][j][3]) * a1;
            }
        }
#pragma unroll
        for (int s = 0; s < 2; ++s)
#pragma unroll
            for (int h = 0; h < 2; ++h) {
                p[s][h] += __shfl_xor_sync(0xffffffffu, p[s][h], 1);
                p[s][h] += __shfl_xor_sync(0xffffffffu, p[s][h], 2);
            }
        __syncthreads();
        if (t == 0) {
#pragma unroll
            for (int s = 0; s < 2; ++s) {
                red[wm + s * 16 + g][w >> 2]     = p[s][0];
                red[wm + s * 16 + g + 8][w >> 2] = p[s][1];
            }
        }
        __syncthreads();
        if (tid < 128) {
            int row = m0 + tid;
            if (row < NLAYER * NN) {
                int node = row % NN, lyr = row / NN;
                g_scores[(size_t)node * NLAYER + lyr] = red[tid][0] + red[tid][1];
            }
        }
    }
}

// ---------------- aggregation: one warp per dst node ----------------
__global__ void agg_kernel(const float* __restrict__ convb, int l) {
    int w = (blockIdx.x * blockDim.x + threadIdx.x) >> 5;
    int lane = threadIdx.x & 31;
    if (w >= NN) return;
    const float* bias = convb + (size_t)l * CDIM;
    const float4* hw4 = (const float4*)g_hW;
    float4 acc = make_float4(0.f, 0.f, 0.f, 0.f);
    int e = g_rowptr[w], e1 = g_rowptr[w + 1];
    for (; e + 1 < e1; e += 2) {
        int s0 = g_col[e];     float w0 = g_ew[e];
        int s1 = g_col[e + 1]; float w1 = g_ew[e + 1];
        float4 v0 = hw4[(size_t)s0 * 32 + lane];
        float4 v1 = hw4[(size_t)s1 * 32 + lane];
        acc.x += w0 * v0.x + w1 * v1.x;
        acc.y += w0 * v0.y + w1 * v1.y;
        acc.z += w0 * v0.z + w1 * v1.z;
        acc.w += w0 * v0.w + w1 * v1.w;
    }
    if (e < e1) {
        int s0 = g_col[e]; float w0 = g_ew[e];
        float4 v0 = hw4[(size_t)s0 * 32 + lane];
        acc.x += w0 * v0.x; acc.y += w0 * v0.y;
        acc.z += w0 * v0.z; acc.w += w0 * v0.w;
    }
    float di = g_dinv[w];
    float sn = di * di;
    float4 sv = hw4[(size_t)w * 32 + lane];
    float4 b  = ((const float4*)bias)[lane];
    float4 r;
    r.x = fmaxf(acc.x + sn * sv.x + b.x, 0.f);
    r.y = fmaxf(acc.y + sn * sv.y + b.y, 0.f);
    r.z = fmaxf(acc.z + sn * sv.z + b.z, 0.f);
    r.w = fmaxf(acc.w + sn * sv.w + b.w, 0.f);
    ((float4*)(g_H + (size_t)l * NN * CDIM))[(size_t)w * 32 + lane] = r;
}

// ---------------- final: softmax over layers + layer-mix + out GEMM ----------------
__global__ __launch_bounds__(256) void final_kernel(const float* __restrict__ Wout,
                                                    const float* __restrict__ bout,
                                                    float* __restrict__ out) {
    __shared__ float At[128][33];
    __shared__ float Ws[128][40];
    __shared__ float sal[128][4];
    int tid = threadIdx.x;
    int m0 = blockIdx.x * 128;

    if (tid < 128) {
        int row = m0 + tid;
        float s0 = 0.f, s1 = 0.f, s2 = 0.f, s3 = 0.f;
        if (row < NN) {
            s0 = g_scores[(size_t)row * 4 + 0];
            s1 = g_scores[(size_t)row * 4 + 1];
            s2 = g_scores[(size_t)row * 4 + 2];
            s3 = g_scores[(size_t)row * 4 + 3];
        }
        float mx = fmaxf(fmaxf(s0, s1), fmaxf(s2, s3));
        float e0 = expf(s0 - mx), e1 = expf(s1 - mx), e2 = expf(s2 - mx), e3 = expf(s3 - mx);
        float inv = 1.0f / (e0 + e1 + e2 + e3);
        sal[tid][0] = e0 * inv; sal[tid][1] = e1 * inv;
        sal[tid][2] = e2 * inv; sal[tid][3] = e3 * inv;
    }
    for (int i = tid; i < 128 * 40; i += 256) Ws[i / 40][i % 40] = Wout[i];
    __syncthreads();

    float acc[4][5];
#pragma unroll
    for (int r = 0; r < 4; ++r)
#pragma unroll
        for (int j = 0; j < 5; ++j) acc[r][j] = 0.f;

    int ty = tid >> 3, tx = tid & 7;
    const size_t LSTR = (size_t)NN * CDIM;

    for (int kc = 0; kc < 128; kc += 32) {
#pragma unroll
        for (int it = 0; it < 4; ++it) {
            int idx = it * 256 + tid;
            int m = idx >> 3, kq = idx & 7;
            int row = m0 + m;
            float4 v = make_float4(0.f, 0.f, 0.f, 0.f);
            if (row < NN) {
                size_t off = (size_t)row * 128 + kc + kq * 4;
                float a0 = sal[m][0], a1 = sal[m][1], a2 = sal[m][2], a3 = sal[m][3];
                float4 h0 = *(const float4*)(g_H + off);
                float4 h1 = *(const float4*)(g_H + off + LSTR);
                float4 h2 = *(const float4*)(g_H + off + 2 * LSTR);
                float4 h3 = *(const float4*)(g_H + off + 3 * LSTR);
                v.x = a0 * h0.x + a1 * h1.x + a2 * h2.x + a3 * h3.x;
                v.y = a0 * h0.y + a1 * h1.y + a2 * h2.y + a3 * h3.y;
                v.z = a0 * h0.z + a1 * h1.z + a2 * h2.z + a3 * h3.z;
                v.w = a0 * h0.w + a1 * h1.w + a2 * h2.w + a3 * h3.w;
            }
            At[m][kq * 4 + 0] = v.x; At[m][kq * 4 + 1] = v.y;
            At[m][kq * 4 + 2] = v.z; At[m][kq * 4 + 3] = v.w;
        }
        __syncthreads();
#pragma unroll
        for (int kk = 0; kk < 32; ++kk) {
            float a[4];
#pragma unroll
            for (int rr = 0; rr < 4; ++rr) a[rr] = At[ty * 4 + rr][kk];
            float b[5];
#pragma unroll
            for (int j = 0; j < 5; ++j) b[j] = Ws[kc + kk][tx * 5 + j];
#pragma unroll
            for (int rr = 0; rr < 4; ++rr)
#pragma unroll
                for (int j = 0; j < 5; ++j) acc[rr][j] += a[rr] * b[j];
        }
        __syncthreads();
    }

#pragma unroll
    for (int rr = 0; rr < 4; ++rr) {
        int row = m0 + ty * 4 + rr;
        if (row < NN) {
#pragma unroll
            for (int j = 0; j < 5; ++j) {
                int col = tx * 5 + j;
                out[(size_t)row * NCLASS + col] = acc[rr][j] + bout[col];
            }
        }
    }
}

// ---------------- launch ----------------
static const void* find_by_size(void* const* d_in, const int* in_sizes, int n_in,
                                long long want, const void* fallback) {
    for (int i = 0; i < n_in; ++i)
        if ((long long)in_sizes[i] == want) return d_in[i];
    return fallback;
}

extern "C" void kernel_launch(void* const* d_in, const int* in_sizes, int n_in,
                              void* d_out, int out_size) {
    const float* x     = (const float*)find_by_size(d_in, in_sizes, n_in, (long long)NN * CDIM, d_in[0]);
    const void*  ei    =               find_by_size(d_in, in_sizes, n_in, 2LL * NE,            d_in[1]);
    const float* convW = (const float*)find_by_size(d_in, in_sizes, n_in, (long long)NLAYER * CDIM * CDIM, d_in[2]);
    const float* convb = (const float*)find_by_size(d_in, in_sizes, n_in, (long long)NLAYER * CDIM, d_in[3]);
    const float* W_att = (const float*)find_by_size(d_in, in_sizes, n_in, (long long)CDIM * CDIM, d_in[4]);
    const float* a_att = (const float*)find_by_size(d_in, in_sizes, n_in, (long long)CDIM, d_in[5]);
    const float* W_out = (const float*)find_by_size(d_in, in_sizes, n_in, (long long)CDIM * NCLASS, d_in[6]);
    const float* b_out = (const float*)find_by_size(d_in, in_sizes, n_in, (long long)NCLASS, d_in[7]);
    float*       out   = (float*)d_out;

    detect_kernel<<<1, 1>>>(ei);
    zero_kernel<<<(NN + 255) / 256, 256>>>();
    hist_kernel<<<(NE + 255) / 256, 256>>>(ei);
    scan1_kernel<<<49, 1024>>>();
    scan2_kernel<<<1, 64>>>();
    scan3_kernel<<<49, 1024>>>();
    scatter_kernel<<<(NE + 255) / 256, 256>>>(ei);
    bprep_kernel<<<(5 * 8192 + 255) / 256, 256>>>(convW, W_att);

    const int GB  = (NN + 127) / 128;            // 391
    const int GBA = (NLAYER * NN + 127) / 128;   // 1563
    for (int l = 0; l < NLAYER; ++l) {
        gemm_kernel<0><<<GB, 256>>>(x, nullptr, l, l == 0 ? 1 : 0);
        agg_kernel<<<(NN * 32 + 255) / 256, 256>>>(convb, l);
    }
    gemm_kernel<1><<<GBA, 256>>>(nullptr, a_att, 0, 0);
    final_kernel<<<GB, 256>>>(W_out, b_out, out);
}

// round 8
// speedup vs baseline: 1.8446x; 1.0631x over previous
#include <cuda_runtime.h>
#include <cuda_bf16.h>
#include <cuda_fp16.h>
#include <math.h>

#define NN 50000
#define NE 800000
#define CDIM 128
#define NLAYER 4
#define NCLASS 40

// ---------------- scratch (device globals; no allocation allowed) ----------------
__device__ int   g_is64;
__device__ int   g_deg[NN];
__device__ int   g_fill[NN];
__device__ int   g_rowptr[NN + 1];
__device__ float g_dinv[NN];
__device__ int   g_bsum[64];
__device__ int   g_boff[64];
__device__ int   g_col[NE];
__device__ __align__(16) float g_ew[NE];
__device__ __align__(16) unsigned g_hWh[(size_t)NN * 64];   // hW rows as half2 (128 halves/row)
__device__ __align__(16) float g_H[(size_t)NLAYER * NN * CDIM];
__device__ __align__(16) float g_scores[(size_t)NN * NLAYER];
// pre-split weights: slot 0..3 = convW layers, slot 4 = W_att; [n][k] bf16x2 u32
__device__ __align__(16) unsigned g_Bh[5 * 128 * 64];
__device__ __align__(16) unsigned g_Bl[5 * 128 * 64];

// ---------------- helpers ----------------
__device__ __forceinline__ unsigned short bf_hi(float x) {
    return __bfloat16_as_ushort(__float2bfloat16(x));
}
__device__ __forceinline__ void split2(float x0, float x1, unsigned& hi, unsigned& lo) {
    unsigned short h0 = bf_hi(x0), h1 = bf_hi(x1);
    float r0 = x0 - __bfloat162float(__ushort_as_bfloat16(h0));
    float r1 = x1 - __bfloat162float(__ushort_as_bfloat16(h1));
    unsigned short l0 = bf_hi(r0), l1 = bf_hi(r1);
    hi = ((unsigned)h1 << 16) | h0;
    lo = ((unsigned)l1 << 16) | l0;
}
__device__ __forceinline__ void mma16816(float& c0, float& c1, float& c2, float& c3,
                                         unsigned a0, unsigned a1, unsigned a2, unsigned a3,
                                         unsigned b0, unsigned b1) {
    asm volatile("mma.sync.aligned.m16n8k16.row.col.f32.bf16.bf16.f32 "
                 "{%0,%1,%2,%3}, {%4,%5,%6,%7}, {%8,%9}, {%0,%1,%2,%3};"
                 : "+f"(c0), "+f"(c1), "+f"(c2), "+f"(c3)
                 : "r"(a0), "r"(a1), "r"(a2), "r"(a3), "r"(b0), "r"(b1));
}
__device__ __forceinline__ unsigned smem_u32(const void* p) {
    unsigned a;
    asm("{ .reg .u64 t; cvta.to.shared.u64 t, %1; cvt.u32.u64 %0, t; }" : "=r"(a) : "l"(p));
    return a;
}
__device__ __forceinline__ void ldsm_x4(unsigned& r0, unsigned& r1, unsigned& r2, unsigned& r3,
                                        unsigned addr) {
    asm volatile("ldmatrix.sync.aligned.m8n8.x4.shared.b16 {%0,%1,%2,%3}, [%4];"
                 : "=r"(r0), "=r"(r1), "=r"(r2), "=r"(r3) : "r"(addr));
}

// ---------------- edge dtype detection ----------------
__global__ void detect_kernel(const void* ei) {
    const long long* p = (const long long*)ei;
    int ok = 1;
    for (int i = 0; i < 8; ++i) {
        long long v = p[i];
        if (v < 0 || v >= NN) ok = 0;
    }
    g_is64 = ok;
}
__device__ __forceinline__ int edge_src(const void* ei, int e) {
    return g_is64 ? (int)((const long long*)ei)[e] : ((const int*)ei)[e];
}
__device__ __forceinline__ int edge_dst(const void* ei, int e) {
    return g_is64 ? (int)((const long long*)ei)[NE + e] : ((const int*)ei)[NE + e];
}

// ---------------- CSR build ----------------
__global__ void zero_kernel() {
    int i = blockIdx.x * blockDim.x + threadIdx.x;
    if (i < NN) { g_deg[i] = 0; g_fill[i] = 0; }
}
__global__ void hist_kernel(const void* __restrict__ ei) {
    int e = blockIdx.x * blockDim.x + threadIdx.x;
    if (e < NE) {
        int d = edge_dst(ei, e);
        if ((unsigned)d < NN) atomicAdd(&g_deg[d], 1);
    }
}
__global__ __launch_bounds__(1024) void scan1_kernel() {
    __shared__ int wsum[32];
    int b = blockIdx.x, t = threadIdx.x;
    int i = b * 1024 + t;
    int lane = t & 31, wid = t >> 5;
    int v = (i < NN) ? g_deg[i] : 0;
    if (i < NN) g_dinv[i] = rsqrtf(1.0f + (float)v);
    int inc = v;
#pragma unroll
    for (int o = 1; o < 32; o <<= 1) {
        int u = __shfl_up_sync(0xffffffffu, inc, o);
        if (lane >= o) inc += u;
    }
    if (lane == 31) wsum[wid] = inc;
    __syncthreads();
    if (wid == 0) {
        int s = wsum[lane];
#pragma unroll
        for (int o = 1; o < 32; o <<= 1) {
            int u = __shfl_up_sync(0xffffffffu, s, o);
            if (lane >= o) s += u;
        }
        wsum[lane] = s;
    }
    __syncthreads();
    int incl = inc + (wid ? wsum[wid - 1] : 0);
    if (i < NN) g_rowptr[i + 1] = incl;
    if (t == 1023) g_bsum[b] = incl;
}
__global__ void scan2_kernel() {
    __shared__ int sm[64];
    int t = threadIdx.x;
    int v = (t < 49) ? g_bsum[t] : 0;
    sm[t] = v;
    __syncthreads();
    for (int o = 1; o < 64; o <<= 1) {
        int u = (t >= o) ? sm[t - o] : 0;
        __syncthreads();
        sm[t] += u;
        __syncthreads();
    }
    g_boff[t] = sm[t] - v;
}
__global__ __launch_bounds__(1024) void scan3_kernel() {
    int b = blockIdx.x, t = threadIdx.x;
    int i = b * 1024 + t;
    if (i < NN) g_rowptr[i + 1] += g_boff[b];
    if (i == 0) g_rowptr[0] = 0;
}
__global__ void scatter_kernel(const void* __restrict__ ei) {
    int e = blockIdx.x * blockDim.x + threadIdx.x;
    if (e < NE) {
        int s = edge_src(ei, e);
        int d = edge_dst(ei, e);
        if ((unsigned)s < NN && (unsigned)d < NN) {
            int pos = g_rowptr[d] + atomicAdd(&g_fill[d], 1);
            g_col[pos] = s;
            g_ew[pos]  = g_dinv[s] * g_dinv[d];
        }
    }
}

// ---------------- B prep: all 5 weight matrices at once ----------------
__global__ void bprep_kernel(const float* __restrict__ convW, const float* __restrict__ Watt) {
    int idx = blockIdx.x * 256 + threadIdx.x;
    if (idx >= 5 * 128 * 64) return;
    int slot = idx >> 13;          // 0..4
    int r = idx & 8191;
    int n = r >> 6, q = r & 63, k = q * 2;
    const float* B = (slot < 4) ? (convW + (size_t)slot * 128 * 128) : Watt;
    float x0 = B[(size_t)k * 128 + n];
    float x1 = B[(size_t)(k + 1) * 128 + n];
    unsigned hi, lo;
    split2(x0, x1, hi, lo);
    g_Bh[slot * 8192 + n * 64 + q] = hi;
    g_Bl[slot * 8192 + n * 64 + q] = lo;
}

// ---------------- tensor-core GEMM (split bf16) ----------------
// ATT==0: A = (use_x ? x : g_H[l-1]) [NN x 128], B = convW[l] -> g_hWh (fp16)
// ATT==1: A = g_H (batched, 4*NN rows), B = W_att -> scores (all layers)
template<int ATT>
__global__ __launch_bounds__(256, 2) void gemm_kernel(const float* __restrict__ x,
                                                      const float* __restrict__ avec,
                                                      int l, int use_x) {
    __shared__ unsigned short Ah[128][40], Al[128][40];   // row stride 80B = 16*5
    __shared__ unsigned short Bh[128][40], Bl[128][40];
    __shared__ float red[128][2];

    const float* A;
    int Mrows;
    if (ATT) { A = g_H; Mrows = NLAYER * NN; }
    else     { A = use_x ? x : (g_H + (size_t)(l - 1) * NN * CDIM); Mrows = NN; }
    const unsigned* GBh = g_Bh + (ATT ? 4 : l) * 8192;
    const unsigned* GBl = g_Bl + (ATT ? 4 : l) * 8192;

    int tid = threadIdx.x;
    int m0 = blockIdx.x * 128;
    int lane = tid & 31, w = tid >> 5;
    int g = lane >> 2, t = lane & 3;
    int wm = (w & 3) * 32, wn = (w >> 2) * 64;

    int mi = lane >> 3, r8 = lane & 7;
    unsigned a_h[2], a_l[2];
#pragma unroll
    for (int s = 0; s < 2; ++s) {
        int row = wm + s * 16 + (mi & 1) * 8 + r8;
        int col = (mi >> 1) * 8;
        a_h[s] = smem_u32(&Ah[row][col]);
        a_l[s] = smem_u32(&Al[row][col]);
    }
    unsigned b_h[4], b_l[4];
#pragma unroll
    for (int jp = 0; jp < 4; ++jp) {
        int row = wn + jp * 16 + (mi >> 1) * 8 + r8;
        int col = (mi & 1) * 8;
        b_h[jp] = smem_u32(&Bh[row][col]);
        b_l[jp] = smem_u32(&Bl[row][col]);
    }

    float c[2][8][4];
#pragma unroll
    for (int s = 0; s < 2; ++s)
#pragma unroll
        for (int j = 0; j < 8; ++j)
#pragma unroll
            for (int q = 0; q < 4; ++q) c[s][j][q] = 0.f;

    float4 pf[4];
#pragma unroll
    for (int it = 0; it < 4; ++it) {
        int idx = it * 256 + tid;
        int m = idx >> 3, q = idx & 7;
        int row = m0 + m;
        pf[it] = make_float4(0.f, 0.f, 0.f, 0.f);
        if (row < Mrows) pf[it] = *(const float4*)(A + (size_t)row * 128 + q * 4);
    }

    for (int kc = 0; kc < 128; kc += 32) {
#pragma unroll
        for (int it = 0; it < 4; ++it) {
            int idx = it * 256 + tid;
            int m = idx >> 3, q = idx & 7;
            unsigned h0, l0, h1, l1;
            split2(pf[it].x, pf[it].y, h0, l0);
            split2(pf[it].z, pf[it].w, h1, l1);
            *(unsigned*)&Ah[m][q * 4]     = h0;
            *(unsigned*)&Ah[m][q * 4 + 2] = h1;
            *(unsigned*)&Al[m][q * 4]     = l0;
            *(unsigned*)&Al[m][q * 4 + 2] = l1;
        }
#pragma unroll
        for (int it = 0; it < 16; ++it) {
            int idx = it * 256 + tid;
            int half = idx >> 11;
            int rr = idx & 2047;
            int n = rr >> 4, q = rr & 15;
            unsigned val = (half ? GBl : GBh)[n * 64 + (kc >> 1) + q];
            if (half) *(unsigned*)&Bl[n][q * 2] = val;
            else      *(unsigned*)&Bh[n][q * 2] = val;
        }
        __syncthreads();

        if (kc < 96) {
#pragma unroll
            for (int it = 0; it < 4; ++it) {
                int idx = it * 256 + tid;
                int m = idx >> 3, q = idx & 7;
                int row = m0 + m;
                pf[it] = make_float4(0.f, 0.f, 0.f, 0.f);
                if (row < Mrows) pf[it] = *(const float4*)(A + (size_t)row * 128 + kc + 32 + q * 4);
            }
        }

#pragma unroll
        for (int ks = 0; ks < 32; ks += 16) {
            unsigned koff = ks * 2;
            unsigned ah[2][4], al[2][4];
#pragma unroll
            for (int s = 0; s < 2; ++s) {
                ldsm_x4(ah[s][0], ah[s][1], ah[s][2], ah[s][3], a_h[s] + koff);
                ldsm_x4(al[s][0], al[s][1], al[s][2], al[s][3], a_l[s] + koff);
            }
#pragma unroll
            for (int jp = 0; jp < 4; ++jp) {
                unsigned bh0, bh1, bh2, bh3, bl0, bl1, bl2, bl3;
                ldsm_x4(bh0, bh1, bh2, bh3, b_h[jp] + koff);
                ldsm_x4(bl0, bl1, bl2, bl3, b_l[jp] + koff);
#pragma unroll
                for (int s = 0; s < 2; ++s) {
                    mma16816(c[s][2 * jp][0], c[s][2 * jp][1], c[s][2 * jp][2], c[s][2 * jp][3],
                             ah[s][0], ah[s][1], ah[s][2], ah[s][3], bh0, bh1);
                    mma16816(c[s][2 * jp][0], c[s][2 * jp][1], c[s][2 * jp][2], c[s][2 * jp][3],
                             ah[s][0], ah[s][1], ah[s][2], ah[s][3], bl0, bl1);
                    mma16816(c[s][2 * jp][0], c[s][2 * jp][1], c[s][2 * jp][2], c[s][2 * jp][3],
                             al[s][0], al[s][1], al[s][2], al[s][3], bh0, bh1);
                    mma16816(c[s][2 * jp + 1][0], c[s][2 * jp + 1][1], c[s][2 * jp + 1][2], c[s][2 * jp + 1][3],
                             ah[s][0], ah[s][1], ah[s][2], ah[s][3], bh2, bh3);
                    mma16816(c[s][2 * jp + 1][0], c[s][2 * jp + 1][1], c[s][2 * jp + 1][2], c[s][2 * jp + 1][3],
                             ah[s][0], ah[s][1], ah[s][2], ah[s][3], bl2, bl3);
                    mma16816(c[s][2 * jp + 1][0], c[s][2 * jp + 1][1], c[s][2 * jp + 1][2], c[s][2 * jp + 1][3],
                             al[s][0], al[s][1], al[s][2], al[s][3], bh2, bh3);
                }
            }
        }
        __syncthreads();
    }

    if (ATT == 0) {
        __half2* C = (__half2*)g_hWh;
#pragma unroll
        for (int s = 0; s < 2; ++s) {
#pragma unroll
            for (int j = 0; j < 8; ++j) {
                int rr = m0 + wm + s * 16 + g;
                int n = wn + j * 8 + 2 * t;        // even
                if (rr < NN)     C[(size_t)rr * 64 + (n >> 1)]       = __floats2half2_rn(c[s][j][0], c[s][j][1]);
                if (rr + 8 < NN) C[(size_t)(rr + 8) * 64 + (n >> 1)] = __floats2half2_rn(c[s][j][2], c[s][j][3]);
            }
        }
    } else {
        float p[2][2] = {{0.f, 0.f}, {0.f, 0.f}};
#pragma unroll
        for (int j = 0; j < 8; ++j) {
            int n = wn + j * 8 + 2 * t;
            float a0 = avec[n], a1 = avec[n + 1];
#pragma unroll
            for (int s = 0; s < 2; ++s) {
                p[s][0] += tanhf(c[s][j][0]) * a0 + tanhf(c[s][j][1]) * a1;
                p[s][1] += tanhf(c[s][j][2]) * a0 + tanhf(c[s][j][3]) * a1;
            }
        }
#pragma unroll
        for (int s = 0; s < 2; ++s)
#pragma unroll
            for (int h = 0; h < 2; ++h) {
                p[s][h] += __shfl_xor_sync(0xffffffffu, p[s][h], 1);
                p[s][h] += __shfl_xor_sync(0xffffffffu, p[s][h], 2);
            }
        __syncthreads();
        if (t == 0) {
#pragma unroll
            for (int s = 0; s < 2; ++s) {
                red[wm + s * 16 + g][w >> 2]     = p[s][0];
                red[wm + s * 16 + g + 8][w >> 2] = p[s][1];
            }
        }
        __syncthreads();
        if (tid < 128) {
            int row = m0 + tid;
            if (row < NLAYER * NN) {
                int node = row % NN, lyr = row / NN;
                g_scores[(size_t)node * NLAYER + lyr] = red[tid][0] + red[tid][1];
            }
        }
    }
}

// ---------------- aggregation: one warp per dst node, fp16 gather ----------------
// lane covers 4 halves (8B): row = 32 lanes * 8B = 256B
__global__ void agg_kernel(const float* __restrict__ convb, int l) {
    int w = (blockIdx.x * blockDim.x + threadIdx.x) >> 5;
    int lane = threadIdx.x & 31;
    if (w >= NN) return;
    const float* bias = convb + (size_t)l * CDIM;
    const uint2* hw = (const uint2*)g_hWh;   // 4 halves per uint2, 32 per row
    float4 acc = make_float4(0.f, 0.f, 0.f, 0.f);
    int e = g_rowptr[w], e1 = g_rowptr[w + 1];
    for (; e + 1 < e1; e += 2) {
        int s0 = g_col[e];     float w0 = g_ew[e];
        int s1 = g_col[e + 1]; float w1 = g_ew[e + 1];
        uint2 u0 = hw[(size_t)s0 * 32 + lane];
        uint2 u1 = hw[(size_t)s1 * 32 + lane];
        float2 a0 = __half22float2(*(__half2*)&u0.x), b0 = __half22float2(*(__half2*)&u0.y);
        float2 a1 = __half22float2(*(__half2*)&u1.x), b1 = __half22float2(*(__half2*)&u1.y);
        acc.x += w0 * a0.x + w1 * a1.x;
        acc.y += w0 * a0.y + w1 * a1.y;
        acc.z += w0 * b0.x + w1 * b1.x;
        acc.w += w0 * b0.y + w1 * b1.y;
    }
    if (e < e1) {
        int s0 = g_col[e]; float w0 = g_ew[e];
        uint2 u0 = hw[(size_t)s0 * 32 + lane];
        float2 a0 = __half22float2(*(__half2*)&u0.x), b0 = __half22float2(*(__half2*)&u0.y);
        acc.x += w0 * a0.x; acc.y += w0 * a0.y;
        acc.z += w0 * b0.x; acc.w += w0 * b0.y;
    }
    float di = g_dinv[w];
    float sn = di * di;
    uint2 us = hw[(size_t)w * 32 + lane];
    float2 s0 = __half22float2(*(__half2*)&us.x), s1 = __half22float2(*(__half2*)&us.y);
    const float4* b4 = (const float4*)bias;
    float4 b = b4[lane];
    float4 r;
    r.x = fmaxf(acc.x + sn * s0.x + b.x, 0.f);
    r.y = fmaxf(acc.y + sn * s0.y + b.y, 0.f);
    r.z = fmaxf(acc.z + sn * s1.x + b.z, 0.f);
    r.w = fmaxf(acc.w + sn * s1.y + b.w, 0.f);
    ((float4*)(g_H + (size_t)l * NN * CDIM))[(size_t)w * 32 + lane] = r;
}

// ---------------- final: softmax over layers + layer-mix + out GEMM ----------------
__global__ __launch_bounds__(256) void final_kernel(const float* __restrict__ Wout,
                                                    const float* __restrict__ bout,
                                                    float* __restrict__ out) {
    __shared__ float At[128][33];
    __shared__ float Ws[128][40];
    __shared__ float sal[128][4];
    int tid = threadIdx.x;
    int m0 = blockIdx.x * 128;

    if (tid < 128) {
        int row = m0 + tid;
        float s0 = 0.f, s1 = 0.f, s2 = 0.f, s3 = 0.f;
        if (row < NN) {
            s0 = g_scores[(size_t)row * 4 + 0];
            s1 = g_scores[(size_t)row * 4 + 1];
            s2 = g_scores[(size_t)row * 4 + 2];
            s3 = g_scores[(size_t)row * 4 + 3];
        }
        float mx = fmaxf(fmaxf(s0, s1), fmaxf(s2, s3));
        float e0 = expf(s0 - mx), e1 = expf(s1 - mx), e2 = expf(s2 - mx), e3 = expf(s3 - mx);
        float inv = 1.0f / (e0 + e1 + e2 + e3);
        sal[tid][0] = e0 * inv; sal[tid][1] = e1 * inv;
        sal[tid][2] = e2 * inv; sal[tid][3] = e3 * inv;
    }
    for (int i = tid; i < 128 * 40; i += 256) Ws[i / 40][i % 40] = Wout[i];
    __syncthreads();

    float acc[4][5];
#pragma unroll
    for (int r = 0; r < 4; ++r)
#pragma unroll
        for (int j = 0; j < 5; ++j) acc[r][j] = 0.f;

    int ty = tid >> 3, tx = tid & 7;
    const size_t LSTR = (size_t)NN * CDIM;

    for (int kc = 0; kc < 128; kc += 32) {
#pragma unroll
        for (int it = 0; it < 4; ++it) {
            int idx = it * 256 + tid;
            int m = idx >> 3, kq = idx & 7;
            int row = m0 + m;
            float4 v = make_float4(0.f, 0.f, 0.f, 0.f);
            if (row < NN) {
                size_t off = (size_t)row * 128 + kc + kq * 4;
                float a0 = sal[m][0], a1 = sal[m][1], a2 = sal[m][2], a3 = sal[m][3];
                float4 h0 = *(const float4*)(g_H + off);
                float4 h1 = *(const float4*)(g_H + off + LSTR);
                float4 h2 = *(const float4*)(g_H + off + 2 * LSTR);
                float4 h3 = *(const float4*)(g_H + off + 3 * LSTR);
                v.x = a0 * h0.x + a1 * h1.x + a2 * h2.x + a3 * h3.x;
                v.y = a0 * h0.y + a1 * h1.y + a2 * h2.y + a3 * h3.y;
                v.z = a0 * h0.z + a1 * h1.z + a2 * h2.z + a3 * h3.z;
                v.w = a0 * h0.w + a1 * h1.w + a2 * h2.w + a3 * h3.w;
            }
            At[m][kq * 4 + 0] = v.x; At[m][kq * 4 + 1] = v.y;
            At[m][kq * 4 + 2] = v.z; At[m][kq * 4 + 3] = v.w;
        }
        __syncthreads();
#pragma unroll
        for (int kk = 0; kk < 32; ++kk) {
            float a[4];
#pragma unroll
            for (int rr = 0; rr < 4; ++rr) a[rr] = At[ty * 4 + rr][kk];
            float b[5];
#pragma unroll
            for (int j = 0; j < 5; ++j) b[j] = Ws[kc + kk][tx * 5 + j];
#pragma unroll
            for (int rr = 0; rr < 4; ++rr)
#pragma unroll
                for (int j = 0; j < 5; ++j) acc[rr][j] += a[rr] * b[j];
        }
        __syncthreads();
    }

#pragma unroll
    for (int rr = 0; rr < 4; ++rr) {
        int row = m0 + ty * 4 + rr;
        if (row < NN) {
#pragma unroll
            for (int j = 0; j < 5; ++j) {
                int col = tx * 5 + j;
                out[(size_t)row * NCLASS + col] = acc[rr][j] + bout[col];
            }
        }
    }
}

// ---------------- launch ----------------
static const void* find_by_size(void* const* d_in, const int* in_sizes, int n_in,
                                long long want, const void* fallback) {
    for (int i = 0; i < n_in; ++i)
        if ((long long)in_sizes[i] == want) return d_in[i];
    return fallback;
}

extern "C" void kernel_launch(void* const* d_in, const int* in_sizes, int n_in,
                              void* d_out, int out_size) {
    const float* x     = (const float*)find_by_size(d_in, in_sizes, n_in, (long long)NN * CDIM, d_in[0]);
    const void*  ei    =               find_by_size(d_in, in_sizes, n_in, 2LL * NE,            d_in[1]);
    const float* convW = (const float*)find_by_size(d_in, in_sizes, n_in, (long long)NLAYER * CDIM * CDIM, d_in[2]);
    const float* convb = (const float*)find_by_size(d_in, in_sizes, n_in, (long long)NLAYER * CDIM, d_in[3]);
    const float* W_att = (const float*)find_by_size(d_in, in_sizes, n_in, (long long)CDIM * CDIM, d_in[4]);
    const float* a_att = (const float*)find_by_size(d_in, in_sizes, n_in, (long long)CDIM, d_in[5]);
    const float* W_out = (const float*)find_by_size(d_in, in_sizes, n_in, (long long)CDIM * NCLASS, d_in[6]);
    const float* b_out = (const float*)find_by_size(d_in, in_sizes, n_in, (long long)NCLASS, d_in[7]);
    float*       out   = (float*)d_out;

    detect_kernel<<<1, 1>>>(ei);
    zero_kernel<<<(NN + 255) / 256, 256>>>();
    hist_kernel<<<(NE + 255) / 256, 256>>>(ei);
    scan1_kernel<<<49, 1024>>>();
    scan2_kernel<<<1, 64>>>();
    scan3_kernel<<<49, 1024>>>();
    scatter_kernel<<<(NE + 255) / 256, 256>>>(ei);
    bprep_kernel<<<(5 * 8192 + 255) / 256, 256>>>(convW, W_att);

    const int GB  = (NN + 127) / 128;            // 391
    const int GBA = (NLAYER * NN + 127) / 128;   // 1563
    for (int l = 0; l < NLAYER; ++l) {
        gemm_kernel<0><<<GB, 256>>>(x, nullptr, l, l == 0 ? 1 : 0);
        agg_kernel<<<(NN * 32 + 255) / 256, 256>>>(convb, l);
    }
    gemm_kernel<1><<<GBA, 256>>>(nullptr, a_att, 0, 0);
    final_kernel<<<GB, 256>>>(W_out, b_out, out);
}

// round 9
// speedup vs baseline: 1.8778x; 1.0180x over previous
#include <cuda_runtime.h>
#include <cuda_bf16.h>
#include <cuda_fp16.h>
#include <math.h>

#define NN 50000
#define NE 800000
#define CDIM 128
#define NLAYER 4
#define NCLASS 40

// ---------------- scratch (device globals; no allocation allowed) ----------------
__device__ int   g_is64;
__device__ int   g_deg[NN];
__device__ int   g_fill[NN];
__device__ int   g_rowptr[NN + 1];
__device__ float g_dinv[NN];
__device__ int   g_bsum[64];
__device__ int   g_boff[64];
__device__ int   g_col[NE];
__device__ __align__(16) float g_ew[NE];
__device__ __align__(16) unsigned g_hWh[(size_t)NN * 64];   // hW rows as half2 (128 halves/row)
__device__ __align__(16) float g_H[(size_t)NLAYER * NN * CDIM];
__device__ __align__(16) float g_scores[(size_t)NN * NLAYER];
// pre-split weights: slot 0..3 = convW layers, slot 4 = W_att; [n][k] bf16x2 u32
__device__ __align__(16) unsigned g_Bh[5 * 128 * 64];
__device__ __align__(16) unsigned g_Bl[5 * 128 * 64];

// ---------------- helpers ----------------
__device__ __forceinline__ unsigned short bf_hi(float x) {
    return __bfloat16_as_ushort(__float2bfloat16(x));
}
__device__ __forceinline__ void split2(float x0, float x1, unsigned& hi, unsigned& lo) {
    unsigned short h0 = bf_hi(x0), h1 = bf_hi(x1);
    float r0 = x0 - __bfloat162float(__ushort_as_bfloat16(h0));
    float r1 = x1 - __bfloat162float(__ushort_as_bfloat16(h1));
    unsigned short l0 = bf_hi(r0), l1 = bf_hi(r1);
    hi = ((unsigned)h1 << 16) | h0;
    lo = ((unsigned)l1 << 16) | l0;
}
__device__ __forceinline__ void mma16816(float& c0, float& c1, float& c2, float& c3,
                                         unsigned a0, unsigned a1, unsigned a2, unsigned a3,
                                         unsigned b0, unsigned b1) {
    asm volatile("mma.sync.aligned.m16n8k16.row.col.f32.bf16.bf16.f32 "
                 "{%0,%1,%2,%3}, {%4,%5,%6,%7}, {%8,%9}, {%0,%1,%2,%3};"
                 : "+f"(c0), "+f"(c1), "+f"(c2), "+f"(c3)
                 : "r"(a0), "r"(a1), "r"(a2), "r"(a3), "r"(b0), "r"(b1));
}
__device__ __forceinline__ unsigned smem_u32(const void* p) {
    unsigned a;
    asm("{ .reg .u64 t; cvta.to.shared.u64 t, %1; cvt.u32.u64 %0, t; }" : "=r"(a) : "l"(p));
    return a;
}
__device__ __forceinline__ void ldsm_x4(unsigned& r0, unsigned& r1, unsigned& r2, unsigned& r3,
                                        unsigned addr) {
    asm volatile("ldmatrix.sync.aligned.m8n8.x4.shared.b16 {%0,%1,%2,%3}, [%4];"
                 : "=r"(r0), "=r"(r1), "=r"(r2), "=r"(r3) : "r"(addr));
}

// ---------------- edge accessors ----------------
__device__ __forceinline__ int edge_src(const void* ei, int e) {
    return g_is64 ? (int)((const long long*)ei)[e] : ((const int*)ei)[e];
}
__device__ __forceinline__ int edge_dst(const void* ei, int e) {
    return g_is64 ? (int)((const long long*)ei)[NE + e] : ((const int*)ei)[NE + e];
}

// ---------------- CSR build ----------------
// zero + dtype detect fused (thread 0 of block 0 does the probe first; g_is64 is
// consumed only by later kernels, so ordering within this grid is safe)
__global__ void zero_kernel(const void* ei) {
    int i = blockIdx.x * blockDim.x + threadIdx.x;
    if (i == 0) {
        const long long* p = (const long long*)ei;
        int ok = 1;
        for (int k = 0; k < 8; ++k) {
            long long v = p[k];
            if (v < 0 || v >= NN) ok = 0;
        }
        g_is64 = ok;
    }
    if (i < NN) { g_deg[i] = 0; g_fill[i] = 0; }
}
__global__ void hist_kernel(const void* __restrict__ ei) {
    int e = blockIdx.x * blockDim.x + threadIdx.x;
    if (e < NE) {
        int d = edge_dst(ei, e);
        if ((unsigned)d < NN) atomicAdd(&g_deg[d], 1);
    }
}
__global__ __launch_bounds__(1024) void scan1_kernel() {
    __shared__ int wsum[32];
    int b = blockIdx.x, t = threadIdx.x;
    int i = b * 1024 + t;
    int lane = t & 31, wid = t >> 5;
    int v = (i < NN) ? g_deg[i] : 0;
    if (i < NN) g_dinv[i] = rsqrtf(1.0f + (float)v);
    int inc = v;
#pragma unroll
    for (int o = 1; o < 32; o <<= 1) {
        int u = __shfl_up_sync(0xffffffffu, inc, o);
        if (lane >= o) inc += u;
    }
    if (lane == 31) wsum[wid] = inc;
    __syncthreads();
    if (wid == 0) {
        int s = wsum[lane];
#pragma unroll
        for (int o = 1; o < 32; o <<= 1) {
            int u = __shfl_up_sync(0xffffffffu, s, o);
            if (lane >= o) s += u;
        }
        wsum[lane] = s;
    }
    __syncthreads();
    int incl = inc + (wid ? wsum[wid - 1] : 0);
    if (i < NN) g_rowptr[i + 1] = incl;
    if (t == 1023) g_bsum[b] = incl;
}
__global__ void scan2_kernel() {
    __shared__ int sm[64];
    int t = threadIdx.x;
    int v = (t < 49) ? g_bsum[t] : 0;
    sm[t] = v;
    __syncthreads();
    for (int o = 1; o < 64; o <<= 1) {
        int u = (t >= o) ? sm[t - o] : 0;
        __syncthreads();
        sm[t] += u;
        __syncthreads();
    }
    g_boff[t] = sm[t] - v;
}
__global__ __launch_bounds__(1024) void scan3_kernel() {
    int b = blockIdx.x, t = threadIdx.x;
    int i = b * 1024 + t;
    if (i < NN) g_rowptr[i + 1] += g_boff[b];
    if (i == 0) g_rowptr[0] = 0;
}
__global__ void scatter_kernel(const void* __restrict__ ei) {
    int e = blockIdx.x * blockDim.x + threadIdx.x;
    if (e < NE) {
        int s = edge_src(ei, e);
        int d = edge_dst(ei, e);
        if ((unsigned)s < NN && (unsigned)d < NN) {
            int pos = g_rowptr[d] + atomicAdd(&g_fill[d], 1);
            g_col[pos] = s;
            g_ew[pos]  = g_dinv[s] * g_dinv[d];
        }
    }
}

// ---------------- B prep: all 5 weight matrices at once ----------------
__global__ void bprep_kernel(const float* __restrict__ convW, const float* __restrict__ Watt) {
    int idx = blockIdx.x * 256 + threadIdx.x;
    if (idx >= 5 * 128 * 64) return;
    int slot = idx >> 13;          // 0..4
    int r = idx & 8191;
    int n = r >> 6, q = r & 63, k = q * 2;
    const float* B = (slot < 4) ? (convW + (size_t)slot * 128 * 128) : Watt;
    float x0 = B[(size_t)k * 128 + n];
    float x1 = B[(size_t)(k + 1) * 128 + n];
    unsigned hi, lo;
    split2(x0, x1, hi, lo);
    g_Bh[slot * 8192 + n * 64 + q] = hi;
    g_Bl[slot * 8192 + n * 64 + q] = lo;
}

// ---------------- tensor-core GEMM (split bf16) ----------------
// ATT==0: A = (use_x ? x : g_H[l-1]) [NN x 128], B = convW[l] -> g_hWh (fp16)
// ATT==1: A = g_H (batched, 4*NN rows), B = W_att -> scores (all layers)
template<int ATT>
__global__ __launch_bounds__(256, 2) void gemm_kernel(const float* __restrict__ x,
                                                      const float* __restrict__ avec,
                                                      int l, int use_x) {
    __shared__ unsigned short Ah[128][40], Al[128][40];   // row stride 80B = 16*5
    __shared__ unsigned short Bh[128][40], Bl[128][40];
    __shared__ float red[128][2];

    const float* A;
    int Mrows;
    if (ATT) { A = g_H; Mrows = NLAYER * NN; }
    else     { A = use_x ? x : (g_H + (size_t)(l - 1) * NN * CDIM); Mrows = NN; }
    const unsigned* GBh = g_Bh + (ATT ? 4 : l) * 8192;
    const unsigned* GBl = g_Bl + (ATT ? 4 : l) * 8192;

    int tid = threadIdx.x;
    int m0 = blockIdx.x * 128;
    int lane = tid & 31, w = tid >> 5;
    int g = lane >> 2, t = lane & 3;
    int wm = (w & 3) * 32, wn = (w >> 2) * 64;

    int mi = lane >> 3, r8 = lane & 7;
    unsigned a_h[2], a_l[2];
#pragma unroll
    for (int s = 0; s < 2; ++s) {
        int row = wm + s * 16 + (mi & 1) * 8 + r8;
        int col = (mi >> 1) * 8;
        a_h[s] = smem_u32(&Ah[row][col]);
        a_l[s] = smem_u32(&Al[row][col]);
    }
    unsigned b_h[4], b_l[4];
#pragma unroll
    for (int jp = 0; jp < 4; ++jp) {
        int row = wn + jp * 16 + (mi >> 1) * 8 + r8;
        int col = (mi & 1) * 8;
        b_h[jp] = smem_u32(&Bh[row][col]);
        b_l[jp] = smem_u32(&Bl[row][col]);
    }

    float c[2][8][4];
#pragma unroll
    for (int s = 0; s < 2; ++s)
#pragma unroll
        for (int j = 0; j < 8; ++j)
#pragma unroll
            for (int q = 0; q < 4; ++q) c[s][j][q] = 0.f;

    float4 pf[4];
#pragma unroll
    for (int it = 0; it < 4; ++it) {
        int idx = it * 256 + tid;
        int m = idx >> 3, q = idx & 7;
        int row = m0 + m;
        pf[it] = make_float4(0.f, 0.f, 0.f, 0.f);
        if (row < Mrows) pf[it] = *(const float4*)(A + (size_t)row * 128 + q * 4);
    }

    for (int kc = 0; kc < 128; kc += 32) {
#pragma unroll
        for (int it = 0; it < 4; ++it) {
            int idx = it * 256 + tid;
            int m = idx >> 3, q = idx & 7;
            unsigned h0, l0, h1, l1;
            split2(pf[it].x, pf[it].y, h0, l0);
            split2(pf[it].z, pf[it].w, h1, l1);
            *(unsigned*)&Ah[m][q * 4]     = h0;
            *(unsigned*)&Ah[m][q * 4 + 2] = h1;
            *(unsigned*)&Al[m][q * 4]     = l0;
            *(unsigned*)&Al[m][q * 4 + 2] = l1;
        }
#pragma unroll
        for (int it = 0; it < 16; ++it) {
            int idx = it * 256 + tid;
            int half = idx >> 11;
            int rr = idx & 2047;
            int n = rr >> 4, q = rr & 15;
            unsigned val = (half ? GBl : GBh)[n * 64 + (kc >> 1) + q];
            if (half) *(unsigned*)&Bl[n][q * 2] = val;
            else      *(unsigned*)&Bh[n][q * 2] = val;
        }
        __syncthreads();

        if (kc < 96) {
#pragma unroll
            for (int it = 0; it < 4; ++it) {
                int idx = it * 256 + tid;
                int m = idx >> 3, q = idx & 7;
                int row = m0 + m;
                pf[it] = make_float4(0.f, 0.f, 0.f, 0.f);
                if (row < Mrows) pf[it] = *(const float4*)(A + (size_t)row * 128 + kc + 32 + q * 4);
            }
        }

#pragma unroll
        for (int ks = 0; ks < 32; ks += 16) {
            unsigned koff = ks * 2;
            unsigned ah[2][4], al[2][4];
#pragma unroll
            for (int s = 0; s < 2; ++s) {
                ldsm_x4(ah[s][0], ah[s][1], ah[s][2], ah[s][3], a_h[s] + koff);
                ldsm_x4(al[s][0], al[s][1], al[s][2], al[s][3], a_l[s] + koff);
            }
#pragma unroll
            for (int jp = 0; jp < 4; ++jp) {
                unsigned bh0, bh1, bh2, bh3, bl0, bl1, bl2, bl3;
                ldsm_x4(bh0, bh1, bh2, bh3, b_h[jp] + koff);
                ldsm_x4(bl0, bl1, bl2, bl3, b_l[jp] + koff);
#pragma unroll
                for (int s = 0; s < 2; ++s) {
                    mma16816(c[s][2 * jp][0], c[s][2 * jp][1], c[s][2 * jp][2], c[s][2 * jp][3],
                             ah[s][0], ah[s][1], ah[s][2], ah[s][3], bh0, bh1);
                    mma16816(c[s][2 * jp][0], c[s][2 * jp][1], c[s][2 * jp][2], c[s][2 * jp][3],
                             ah[s][0], ah[s][1], ah[s][2], ah[s][3], bl0, bl1);
                    mma16816(c[s][2 * jp][0], c[s][2 * jp][1], c[s][2 * jp][2], c[s][2 * jp][3],
                             al[s][0], al[s][1], al[s][2], al[s][3], bh0, bh1);
                    mma16816(c[s][2 * jp + 1][0], c[s][2 * jp + 1][1], c[s][2 * jp + 1][2], c[s][2 * jp + 1][3],
                             ah[s][0], ah[s][1], ah[s][2], ah[s][3], bh2, bh3);
                    mma16816(c[s][2 * jp + 1][0], c[s][2 * jp + 1][1], c[s][2 * jp + 1][2], c[s][2 * jp + 1][3],
                             ah[s][0], ah[s][1], ah[s][2], ah[s][3], bl2, bl3);
                    mma16816(c[s][2 * jp + 1][0], c[s][2 * jp + 1][1], c[s][2 * jp + 1][2], c[s][2 * jp + 1][3],
                             al[s][0], al[s][1], al[s][2], al[s][3], bh2, bh3);
                }
            }
        }
        __syncthreads();
    }

    if (ATT == 0) {
        __half2* C = (__half2*)g_hWh;
#pragma unroll
        for (int s = 0; s < 2; ++s) {
#pragma unroll
            for (int j = 0; j < 8; ++j) {
                int rr = m0 + wm + s * 16 + g;
                int n = wn + j * 8 + 2 * t;        // even
                if (rr < NN)     C[(size_t)rr * 64 + (n >> 1)]       = __floats2half2_rn(c[s][j][0], c[s][j][1]);
                if (rr + 8 < NN) C[(size_t)(rr + 8) * 64 + (n >> 1)] = __floats2half2_rn(c[s][j][2], c[s][j][3]);
            }
        }
    } else {
        float p[2][2] = {{0.f, 0.f}, {0.f, 0.f}};
#pragma unroll
        for (int j = 0; j < 8; ++j) {
            int n = wn + j * 8 + 2 * t;
            float a0 = avec[n], a1 = avec[n + 1];
#pragma unroll
            for (int s = 0; s < 2; ++s) {
                p[s][0] += tanhf(c[s][j][0]) * a0 + tanhf(c[s][j][1]) * a1;
                p[s][1] += tanhf(c[s][j][2]) * a0 + tanhf(c[s][j][3]) * a1;
            }
        }
#pragma unroll
        for (int s = 0; s < 2; ++s)
#pragma unroll
            for (int h = 0; h < 2; ++h) {
                p[s][h] += __shfl_xor_sync(0xffffffffu, p[s][h], 1);
                p[s][h] += __shfl_xor_sync(0xffffffffu, p[s][h], 2);
            }
        __syncthreads();
        if (t == 0) {
#pragma unroll
            for (int s = 0; s < 2; ++s) {
                red[wm + s * 16 + g][w >> 2]     = p[s][0];
                red[wm + s * 16 + g + 8][w >> 2] = p[s][1];
            }
        }
        __syncthreads();
        if (tid < 128) {
            int row = m0 + tid;
            if (row < NLAYER * NN) {
                int node = row % NN, lyr = row / NN;
                g_scores[(size_t)node * NLAYER + lyr] = red[tid][0] + red[tid][1];
            }
        }
    }
}

// ---------------- aggregation: one warp per dst node, fp16 gather, 4-edge MLP ----------------
__global__ __launch_bounds__(256) void agg_kernel(const float* __restrict__ convb, int l) {
    int w = (blockIdx.x * blockDim.x + threadIdx.x) >> 5;
    int lane = threadIdx.x & 31;
    if (w >= NN) return;
    const float* bias = convb + (size_t)l * CDIM;
    const uint2* hw = (const uint2*)g_hWh;   // 4 halves per uint2, 32 per row
    float4 acc = make_float4(0.f, 0.f, 0.f, 0.f);
    int e = g_rowptr[w], e1 = g_rowptr[w + 1];

    // 4-edge unrolled main loop: 4 independent gathers in flight
    for (; e + 3 < e1; e += 4) {
        int s0 = g_col[e],     s1 = g_col[e + 1], s2 = g_col[e + 2], s3 = g_col[e + 3];
        float w0 = g_ew[e],    w1 = g_ew[e + 1],  w2 = g_ew[e + 2],  w3 = g_ew[e + 3];
        uint2 u0 = hw[(size_t)s0 * 32 + lane];
        uint2 u1 = hw[(size_t)s1 * 32 + lane];
        uint2 u2 = hw[(size_t)s2 * 32 + lane];
        uint2 u3 = hw[(size_t)s3 * 32 + lane];
        float2 a0 = __half22float2(*(__half2*)&u0.x), b0 = __half22float2(*(__half2*)&u0.y);
        float2 a1 = __half22float2(*(__half2*)&u1.x), b1 = __half22float2(*(__half2*)&u1.y);
        float2 a2 = __half22float2(*(__half2*)&u2.x), b2 = __half22float2(*(__half2*)&u2.y);
        float2 a3 = __half22float2(*(__half2*)&u3.x), b3 = __half22float2(*(__half2*)&u3.y);
        acc.x += w0 * a0.x + w1 * a1.x + w2 * a2.x + w3 * a3.x;
        acc.y += w0 * a0.y + w1 * a1.y + w2 * a2.y + w3 * a3.y;
        acc.z += w0 * b0.x + w1 * b1.x + w2 * b2.x + w3 * b3.x;
        acc.w += w0 * b0.y + w1 * b1.y + w2 * b2.y + w3 * b3.y;
    }
    if (e + 1 < e1) {
        int s0 = g_col[e], s1 = g_col[e + 1];
        float w0 = g_ew[e], w1 = g_ew[e + 1];
        uint2 u0 = hw[(size_t)s0 * 32 + lane];
        uint2 u1 = hw[(size_t)s1 * 32 + lane];
        float2 a0 = __half22float2(*(__half2*)&u0.x), b0 = __half22float2(*(__half2*)&u0.y);
        float2 a1 = __half22float2(*(__half2*)&u1.x), b1 = __half22float2(*(__half2*)&u1.y);
        acc.x += w0 * a0.x + w1 * a1.x;
        acc.y += w0 * a0.y + w1 * a1.y;
        acc.z += w0 * b0.x + w1 * b1.x;
        acc.w += w0 * b0.y + w1 * b1.y;
        e += 2;
    }
    if (e < e1) {
        int s0 = g_col[e]; float w0 = g_ew[e];
        uint2 u0 = hw[(size_t)s0 * 32 + lane];
        float2 a0 = __half22float2(*(__half2*)&u0.x), b0 = __half22float2(*(__half2*)&u0.y);
        acc.x += w0 * a0.x; acc.y += w0 * a0.y;
        acc.z += w0 * b0.x; acc.w += w0 * b0.y;
    }
    float di = g_dinv[w];
    float sn = di * di;
    uint2 us = hw[(size_t)w * 32 + lane];
    float2 s0 = __half22float2(*(__half2*)&us.x), s1 = __half22float2(*(__half2*)&us.y);
    const float4* b4 = (const float4*)bias;
    float4 b = b4[lane];
    float4 r;
    r.x = fmaxf(acc.x + sn * s0.x + b.x, 0.f);
    r.y = fmaxf(acc.y + sn * s0.y + b.y, 0.f);
    r.z = fmaxf(acc.z + sn * s1.x + b.z, 0.f);
    r.w = fmaxf(acc.w + sn * s1.y + b.w, 0.f);
    ((float4*)(g_H + (size_t)l * NN * CDIM))[(size_t)w * 32 + lane] = r;
}

// ---------------- final: softmax over layers + layer-mix + out GEMM ----------------
__global__ __launch_bounds__(256) void final_kernel(const float* __restrict__ Wout,
                                                    const float* __restrict__ bout,
                                                    float* __restrict__ out) {
    __shared__ float At[128][33];
    __shared__ float Ws[128][40];
    __shared__ float sal[128][4];
    int tid = threadIdx.x;
    int m0 = blockIdx.x * 128;

    if (tid < 128) {
        int row = m0 + tid;
        float s0 = 0.f, s1 = 0.f, s2 = 0.f, s3 = 0.f;
        if (row < NN) {
            s0 = g_scores[(size_t)row * 4 + 0];
            s1 = g_scores[(size_t)row * 4 + 1];
            s2 = g_scores[(size_t)row * 4 + 2];
            s3 = g_scores[(size_t)row * 4 + 3];
        }
        float mx = fmaxf(fmaxf(s0, s1), fmaxf(s2, s3));
        float e0 = expf(s0 - mx), e1 = expf(s1 - mx), e2 = expf(s2 - mx), e3 = expf(s3 - mx);
        float inv = 1.0f / (e0 + e1 + e2 + e3);
        sal[tid][0] = e0 * inv; sal[tid][1] = e1 * inv;
        sal[tid][2] = e2 * inv; sal[tid][3] = e3 * inv;
    }
    for (int i = tid; i < 128 * 40; i += 256) Ws[i / 40][i % 40] = Wout[i];
    __syncthreads();

    float acc[4][5];
#pragma unroll
    for (int r = 0; r < 4; ++r)
#pragma unroll
        for (int j = 0; j < 5; ++j) acc[r][j] = 0.f;

    int ty = tid >> 3, tx = tid & 7;
    const size_t LSTR = (size_t)NN * CDIM;

    for (int kc = 0; kc < 128; kc += 32) {
#pragma unroll
        for (int it = 0; it < 4; ++it) {
            int idx = it * 256 + tid;
            int m = idx >> 3, kq = idx & 7;
            int row = m0 + m;
            float4 v = make_float4(0.f, 0.f, 0.f, 0.f);
            if (row < NN) {
                size_t off = (size_t)row * 128 + kc + kq * 4;
                float a0 = sal[m][0], a1 = sal[m][1], a2 = sal[m][2], a3 = sal[m][3];
                float4 h0 = *(const float4*)(g_H + off);
                float4 h1 = *(const float4*)(g_H + off + LSTR);
                float4 h2 = *(const float4*)(g_H + off + 2 * LSTR);
                float4 h3 = *(const float4*)(g_H + off + 3 * LSTR);
                v.x = a0 * h0.x + a1 * h1.x + a2 * h2.x + a3 * h3.x;
                v.y = a0 * h0.y + a1 * h1.y + a2 * h2.y + a3 * h3.y;
                v.z = a0 * h0.z + a1 * h1.z + a2 * h2.z + a3 * h3.z;
                v.w = a0 * h0.w + a1 * h1.w + a2 * h2.w + a3 * h3.w;
            }
            At[m][kq * 4 + 0] = v.x; At[m][kq * 4 + 1] = v.y;
            At[m][kq * 4 + 2] = v.z; At[m][kq * 4 + 3] = v.w;
        }
        __syncthreads();
#pragma unroll
        for (int kk = 0; kk < 32; ++kk) {
            float a[4];
#pragma unroll
            for (int rr = 0; rr < 4; ++rr) a[rr] = At[ty * 4 + rr][kk];
            float b[5];
#pragma unroll
            for (int j = 0; j < 5; ++j) b[j] = Ws[kc + kk][tx * 5 + j];
#pragma unroll
            for (int rr = 0; rr < 4; ++rr)
#pragma unroll
                for (int j = 0; j < 5; ++j) acc[rr][j] += a[rr] * b[j];
        }
        __syncthreads();
    }

#pragma unroll
    for (int rr = 0; rr < 4; ++rr) {
        int row = m0 + ty * 4 + rr;
        if (row < NN) {
#pragma unroll
            for (int j = 0; j < 5; ++j) {
                int col = tx * 5 + j;
                out[(size_t)row * NCLASS + col] = acc[rr][j] + bout[col];
            }
        }
    }
}

// ---------------- launch ----------------
static const void* find_by_size(void* const* d_in, const int* in_sizes, int n_in,
                                long long want, const void* fallback) {
    for (int i = 0; i < n_in; ++i)
        if ((long long)in_sizes[i] == want) return d_in[i];
    return fallback;
}

extern "C" void kernel_launch(void* const* d_in, const int* in_sizes, int n_in,
                              void* d_out, int out_size) {
    const float* x     = (const float*)find_by_size(d_in, in_sizes, n_in, (long long)NN * CDIM, d_in[0]);
    const void*  ei    =               find_by_size(d_in, in_sizes, n_in, 2LL * NE,            d_in[1]);
    const float* convW = (const float*)find_by_size(d_in, in_sizes, n_in, (long long)NLAYER * CDIM * CDIM, d_in[2]);
    const float* convb = (const float*)find_by_size(d_in, in_sizes, n_in, (long long)NLAYER * CDIM, d_in[3]);
    const float* W_att = (const float*)find_by_size(d_in, in_sizes, n_in, (long long)CDIM * CDIM, d_in[4]);
    const float* a_att = (const float*)find_by_size(d_in, in_sizes, n_in, (long long)CDIM, d_in[5]);
    const float* W_out = (const float*)find_by_size(d_in, in_sizes, n_in, (long long)CDIM * NCLASS, d_in[6]);
    const float* b_out = (const float*)find_by_size(d_in, in_sizes, n_in, (long long)NCLASS, d_in[7]);
    float*       out   = (float*)d_out;

    zero_kernel<<<(NN + 255) / 256, 256>>>(ei);
    hist_kernel<<<(NE + 255) / 256, 256>>>(ei);
    scan1_kernel<<<49, 1024>>>();
    scan2_kernel<<<1, 64>>>();
    scan3_kernel<<<49, 1024>>>();
    scatter_kernel<<<(NE + 255) / 256, 256>>>(ei);
    bprep_kernel<<<(5 * 8192 + 255) / 256, 256>>>(convW, W_att);

    const int GB  = (NN + 127) / 128;            // 391
    const int GBA = (NLAYER * NN + 127) / 128;   // 1563
    for (int l = 0; l < NLAYER; ++l) {
        gemm_kernel<0><<<GB, 256>>>(x, nullptr, l, l == 0 ? 1 : 0);
        agg_kernel<<<(NN * 32 + 255) / 256, 256>>>(convb, l);
    }
    gemm_kernel<1><<<GBA, 256>>>(nullptr, a_att, 0, 0);
    final_kernel<<<GB, 256>>>(W_out, b_out, out);
}

// round 10
// speedup vs baseline: 1.9475x; 1.0371x over previous
#include <cuda_runtime.h>
#include <cuda_bf16.h>
#include <cuda_fp16.h>
#include <math.h>

#define NN 50000
#define NE 800000
#define CDIM 128
#define NLAYER 4
#define NCLASS 40

// ---------------- scratch (device globals; no allocation allowed) ----------------
__device__ int   g_is64;
__device__ int   g_deg[NN];
__device__ int   g_fill[NN];
__device__ int   g_rowptr[NN + 1];
__device__ float g_dinv[NN];
__device__ int   g_bsum[64];
__device__ __align__(16) int2 g_cew[NE];                    // (src, bitcast ew) per edge
__device__ __align__(16) unsigned g_hWh[(size_t)NN * 64];   // hW rows as half2 (128 halves/row)
__device__ __align__(16) float g_H[(size_t)NLAYER * NN * CDIM];
__device__ __align__(16) float g_scores[(size_t)NN * NLAYER];
// pre-split weights: slot 0..3 = convW layers, slot 4 = W_att; [n][k] bf16x2 u32
__device__ __align__(16) unsigned g_Bh[5 * 128 * 64];
__device__ __align__(16) unsigned g_Bl[5 * 128 * 64];

// ---------------- helpers ----------------
__device__ __forceinline__ unsigned short bf_hi(float x) {
    return __bfloat16_as_ushort(__float2bfloat16(x));
}
__device__ __forceinline__ void split2(float x0, float x1, unsigned& hi, unsigned& lo) {
    unsigned short h0 = bf_hi(x0), h1 = bf_hi(x1);
    float r0 = x0 - __bfloat162float(__ushort_as_bfloat16(h0));
    float r1 = x1 - __bfloat162float(__ushort_as_bfloat16(h1));
    unsigned short l0 = bf_hi(r0), l1 = bf_hi(r1);
    hi = ((unsigned)h1 << 16) | h0;
    lo = ((unsigned)l1 << 16) | l0;
}
__device__ __forceinline__ void mma16816(float& c0, float& c1, float& c2, float& c3,
                                         unsigned a0, unsigned a1, unsigned a2, unsigned a3,
                                         unsigned b0, unsigned b1) {
    asm volatile("mma.sync.aligned.m16n8k16.row.col.f32.bf16.bf16.f32 "
                 "{%0,%1,%2,%3}, {%4,%5,%6,%7}, {%8,%9}, {%0,%1,%2,%3};"
                 : "+f"(c0), "+f"(c1), "+f"(c2), "+f"(c3)
                 : "r"(a0), "r"(a1), "r"(a2), "r"(a3), "r"(b0), "r"(b1));
}
__device__ __forceinline__ unsigned smem_u32(const void* p) {
    unsigned a;
    asm("{ .reg .u64 t; cvta.to.shared.u64 t, %1; cvt.u32.u64 %0, t; }" : "=r"(a) : "l"(p));
    return a;
}
__device__ __forceinline__ void ldsm_x4(unsigned& r0, unsigned& r1, unsigned& r2, unsigned& r3,
                                        unsigned addr) {
    asm volatile("ldmatrix.sync.aligned.m8n8.x4.shared.b16 {%0,%1,%2,%3}, [%4];"
                 : "=r"(r0), "=r"(r1), "=r"(r2), "=r"(r3) : "r"(addr));
}

// ---------------- edge accessors ----------------
__device__ __forceinline__ int edge_src(const void* ei, int e) {
    return g_is64 ? (int)((const long long*)ei)[e] : ((const int*)ei)[e];
}
__device__ __forceinline__ int edge_dst(const void* ei, int e) {
    return g_is64 ? (int)((const long long*)ei)[NE + e] : ((const int*)ei)[NE + e];
}

// ---------------- CSR build ----------------
__global__ void zero_kernel(const void* ei) {
    int i = blockIdx.x * blockDim.x + threadIdx.x;
    if (i == 0) {
        const long long* p = (const long long*)ei;
        int ok = 1;
        for (int k = 0; k < 8; ++k) {
            long long v = p[k];
            if (v < 0 || v >= NN) ok = 0;
        }
        g_is64 = ok;
    }
    if (i < NN) { g_deg[i] = 0; g_fill[i] = 0; }
}
__global__ void hist_kernel(const void* __restrict__ ei) {
    int e = blockIdx.x * blockDim.x + threadIdx.x;
    if (e < NE) {
        int d = edge_dst(ei, e);
        if ((unsigned)d < NN) atomicAdd(&g_deg[d], 1);
    }
}
__global__ __launch_bounds__(1024) void scan1_kernel() {
    __shared__ int wsum[32];
    int b = blockIdx.x, t = threadIdx.x;
    int i = b * 1024 + t;
    int lane = t & 31, wid = t >> 5;
    int v = (i < NN) ? g_deg[i] : 0;
    if (i < NN) g_dinv[i] = rsqrtf(1.0f + (float)v);
    int inc = v;
#pragma unroll
    for (int o = 1; o < 32; o <<= 1) {
        int u = __shfl_up_sync(0xffffffffu, inc, o);
        if (lane >= o) inc += u;
    }
    if (lane == 31) wsum[wid] = inc;
    __syncthreads();
    if (wid == 0) {
        int s = wsum[lane];
#pragma unroll
        for (int o = 1; o < 32; o <<= 1) {
            int u = __shfl_up_sync(0xffffffffu, s, o);
            if (lane >= o) s += u;
        }
        wsum[lane] = s;
    }
    __syncthreads();
    int incl = inc + (wid ? wsum[wid - 1] : 0);
    if (i < NN) g_rowptr[i + 1] = incl;
    if (t == 1023) g_bsum[b] = incl;
}
// scan of the 49 block sums folded in (each block recomputes it; 6 barrier steps)
__global__ __launch_bounds__(1024) void scan3_kernel() {
    __shared__ int sm[64];
    int b = blockIdx.x, t = threadIdx.x;
    if (t < 64) sm[t] = (t < 49) ? g_bsum[t] : 0;
    __syncthreads();
    for (int o = 1; o < 64; o <<= 1) {
        int u = (t < 64 && t >= o) ? sm[t - o] : 0;
        __syncthreads();
        if (t < 64) sm[t] += u;
        __syncthreads();
    }
    int add = (b == 0) ? 0 : sm[b - 1];
    int i = b * 1024 + t;
    if (i < NN) g_rowptr[i + 1] += add;
    if (i == 0) g_rowptr[0] = 0;
}
__global__ void scatter_kernel(const void* __restrict__ ei) {
    int e = blockIdx.x * blockDim.x + threadIdx.x;
    if (e < NE) {
        int s = edge_src(ei, e);
        int d = edge_dst(ei, e);
        if ((unsigned)s < NN && (unsigned)d < NN) {
            int pos = g_rowptr[d] + atomicAdd(&g_fill[d], 1);
            g_cew[pos] = make_int2(s, __float_as_int(g_dinv[s] * g_dinv[d]));
        }
    }
}

// ---------------- B prep: all 5 weight matrices at once ----------------
__global__ void bprep_kernel(const float* __restrict__ convW, const float* __restrict__ Watt) {
    int idx = blockIdx.x * 256 + threadIdx.x;
    if (idx >= 5 * 128 * 64) return;
    int slot = idx >> 13;          // 0..4
    int r = idx & 8191;
    int n = r >> 6, q = r & 63, k = q * 2;
    const float* B = (slot < 4) ? (convW + (size_t)slot * 128 * 128) : Watt;
    float x0 = B[(size_t)k * 128 + n];
    float x1 = B[(size_t)(k + 1) * 128 + n];
    unsigned hi, lo;
    split2(x0, x1, hi, lo);
    g_Bh[slot * 8192 + n * 64 + q] = hi;
    g_Bl[slot * 8192 + n * 64 + q] = lo;
}

// ---------------- tensor-core GEMM (split bf16), dual-role launch ----------------
// Blocks [0, nconv) compute conv: A @ convW[conv_slot] -> g_hWh (fp16)
// Blocks [nconv, grid) compute att: tanh(A @ W_att) . avec -> g_scores[:, att_layer]
// A = (a_layer < 0 ? x : g_H[a_layer]); both roles read the SAME A.
__global__ __launch_bounds__(256, 2) void gemm_kernel(const float* __restrict__ x,
                                                      const float* __restrict__ avec,
                                                      int a_layer, int conv_slot,
                                                      int att_layer, int nconv) {
    __shared__ unsigned short Ah[128][40], Al[128][40];   // row stride 80B = 16*5
    __shared__ unsigned short Bh[128][40], Bl[128][40];
    __shared__ float red[128][2];

    bool is_att = ((int)blockIdx.x >= nconv);
    int blk = is_att ? (int)blockIdx.x - nconv : (int)blockIdx.x;
    const float* A = (a_layer < 0) ? x : (g_H + (size_t)a_layer * NN * CDIM);
    int slot = is_att ? 4 : conv_slot;
    const unsigned* GBh = g_Bh + slot * 8192;
    const unsigned* GBl = g_Bl + slot * 8192;

    int tid = threadIdx.x;
    int m0 = blk * 128;
    int lane = tid & 31, w = tid >> 5;
    int g = lane >> 2, t = lane & 3;
    int wm = (w & 3) * 32, wn = (w >> 2) * 64;

    int mi = lane >> 3, r8 = lane & 7;
    unsigned a_h[2], a_l[2];
#pragma unroll
    for (int s = 0; s < 2; ++s) {
        int row = wm + s * 16 + (mi & 1) * 8 + r8;
        int col = (mi >> 1) * 8;
        a_h[s] = smem_u32(&Ah[row][col]);
        a_l[s] = smem_u32(&Al[row][col]);
    }
    unsigned b_h[4], b_l[4];
#pragma unroll
    for (int jp = 0; jp < 4; ++jp) {
        int row = wn + jp * 16 + (mi >> 1) * 8 + r8;
        int col = (mi & 1) * 8;
        b_h[jp] = smem_u32(&Bh[row][col]);
        b_l[jp] = smem_u32(&Bl[row][col]);
    }

    float c[2][8][4];
#pragma unroll
    for (int s = 0; s < 2; ++s)
#pragma unroll
        for (int j = 0; j < 8; ++j)
#pragma unroll
            for (int q = 0; q < 4; ++q) c[s][j][q] = 0.f;

    float4 pf[4];
#pragma unroll
    for (int it = 0; it < 4; ++it) {
        int idx = it * 256 + tid;
        int m = idx >> 3, q = idx & 7;
        int row = m0 + m;
        pf[it] = make_float4(0.f, 0.f, 0.f, 0.f);
        if (row < NN) pf[it] = *(const float4*)(A + (size_t)row * 128 + q * 4);
    }

    for (int kc = 0; kc < 128; kc += 32) {
#pragma unroll
        for (int it = 0; it < 4; ++it) {
            int idx = it * 256 + tid;
            int m = idx >> 3, q = idx & 7;
            unsigned h0, l0, h1, l1;
            split2(pf[it].x, pf[it].y, h0, l0);
            split2(pf[it].z, pf[it].w, h1, l1);
            *(unsigned*)&Ah[m][q * 4]     = h0;
            *(unsigned*)&Ah[m][q * 4 + 2] = h1;
            *(unsigned*)&Al[m][q * 4]     = l0;
            *(unsigned*)&Al[m][q * 4 + 2] = l1;
        }
#pragma unroll
        for (int it = 0; it < 16; ++it) {
            int idx = it * 256 + tid;
            int half = idx >> 11;
            int rr = idx & 2047;
            int n = rr >> 4, q = rr & 15;
            unsigned val = (half ? GBl : GBh)[n * 64 + (kc >> 1) + q];
            if (half) *(unsigned*)&Bl[n][q * 2] = val;
            else      *(unsigned*)&Bh[n][q * 2] = val;
        }
        __syncthreads();

        if (kc < 96) {
#pragma unroll
            for (int it = 0; it < 4; ++it) {
                int idx = it * 256 + tid;
                int m = idx >> 3, q = idx & 7;
                int row = m0 + m;
                pf[it] = make_float4(0.f, 0.f, 0.f, 0.f);
                if (row < NN) pf[it] = *(const float4*)(A + (size_t)row * 128 + kc + 32 + q * 4);
            }
        }

#pragma unroll
        for (int ks = 0; ks < 32; ks += 16) {
            unsigned koff = ks * 2;
            unsigned ah[2][4], al[2][4];
#pragma unroll
            for (int s = 0; s < 2; ++s) {
                ldsm_x4(ah[s][0], ah[s][1], ah[s][2], ah[s][3], a_h[s] + koff);
                ldsm_x4(al[s][0], al[s][1], al[s][2], al[s][3], a_l[s] + koff);
            }
#pragma unroll
            for (int jp = 0; jp < 4; ++jp) {
                unsigned bh0, bh1, bh2, bh3, bl0, bl1, bl2, bl3;
                ldsm_x4(bh0, bh1, bh2, bh3, b_h[jp] + koff);
                ldsm_x4(bl0, bl1, bl2, bl3, b_l[jp] + koff);
#pragma unroll
                for (int s = 0; s < 2; ++s) {
                    mma16816(c[s][2 * jp][0], c[s][2 * jp][1], c[s][2 * jp][2], c[s][2 * jp][3],
                             ah[s][0], ah[s][1], ah[s][2], ah[s][3], bh0, bh1);
                    mma16816(c[s][2 * jp][0], c[s][2 * jp][1], c[s][2 * jp][2], c[s][2 * jp][3],
                             ah[s][0], ah[s][1], ah[s][2], ah[s][3], bl0, bl1);
                    mma16816(c[s][2 * jp][0], c[s][2 * jp][1], c[s][2 * jp][2], c[s][2 * jp][3],
                             al[s][0], al[s][1], al[s][2], al[s][3], bh0, bh1);
                    mma16816(c[s][2 * jp + 1][0], c[s][2 * jp + 1][1], c[s][2 * jp + 1][2], c[s][2 * jp + 1][3],
                             ah[s][0], ah[s][1], ah[s][2], ah[s][3], bh2, bh3);
                    mma16816(c[s][2 * jp + 1][0], c[s][2 * jp + 1][1], c[s][2 * jp + 1][2], c[s][2 * jp + 1][3],
                             ah[s][0], ah[s][1], ah[s][2], ah[s][3], bl2, bl3);
                    mma16816(c[s][2 * jp + 1][0], c[s][2 * jp + 1][1], c[s][2 * jp + 1][2], c[s][2 * jp + 1][3],
                             al[s][0], al[s][1], al[s][2], al[s][3], bh2, bh3);
                }
            }
        }
        __syncthreads();
    }

    if (!is_att) {
        __half2* C = (__half2*)g_hWh;
#pragma unroll
        for (int s = 0; s < 2; ++s) {
#pragma unroll
            for (int j = 0; j < 8; ++j) {
                int rr = m0 + wm + s * 16 + g;
                int n = wn + j * 8 + 2 * t;        // even
                if (rr < NN)     C[(size_t)rr * 64 + (n >> 1)]       = __floats2half2_rn(c[s][j][0], c[s][j][1]);
                if (rr + 8 < NN) C[(size_t)(rr + 8) * 64 + (n >> 1)] = __floats2half2_rn(c[s][j][2], c[s][j][3]);
            }
        }
    } else {
        float p[2][2] = {{0.f, 0.f}, {0.f, 0.f}};
#pragma unroll
        for (int j = 0; j < 8; ++j) {
            int n = wn + j * 8 + 2 * t;
            float a0 = avec[n], a1 = avec[n + 1];
#pragma unroll
            for (int s = 0; s < 2; ++s) {
                p[s][0] += tanhf(c[s][j][0]) * a0 + tanhf(c[s][j][1]) * a1;
                p[s][1] += tanhf(c[s][j][2]) * a0 + tanhf(c[s][j][3]) * a1;
            }
        }
#pragma unroll
        for (int s = 0; s < 2; ++s)
#pragma unroll
            for (int h = 0; h < 2; ++h) {
                p[s][h] += __shfl_xor_sync(0xffffffffu, p[s][h], 1);
                p[s][h] += __shfl_xor_sync(0xffffffffu, p[s][h], 2);
            }
        __syncthreads();
        if (t == 0) {
#pragma unroll
            for (int s = 0; s < 2; ++s) {
                red[wm + s * 16 + g][w >> 2]     = p[s][0];
                red[wm + s * 16 + g + 8][w >> 2] = p[s][1];
            }
        }
        __syncthreads();
        if (tid < 128) {
            int row = m0 + tid;
            if (row < NN)
                g_scores[(size_t)row * NLAYER + att_layer] = red[tid][0] + red[tid][1];
        }
    }
}

// ---------------- aggregation: one warp per dst node, fp16 gather, 4-edge MLP ----------------
__global__ __launch_bounds__(256) void agg_kernel(const float* __restrict__ convb, int l) {
    int w = (blockIdx.x * blockDim.x + threadIdx.x) >> 5;
    int lane = threadIdx.x & 31;
    if (w >= NN) return;
    const float* bias = convb + (size_t)l * CDIM;
    const uint2* hw = (const uint2*)g_hWh;   // 4 halves per uint2, 32 per row
    const int2* cew = g_cew;
    float4 acc = make_float4(0.f, 0.f, 0.f, 0.f);
    int e = g_rowptr[w], e1 = g_rowptr[w + 1];

    for (; e + 3 < e1; e += 4) {
        int2 c0 = cew[e], c1 = cew[e + 1], c2 = cew[e + 2], c3 = cew[e + 3];
        uint2 u0 = hw[(size_t)c0.x * 32 + lane];
        uint2 u1 = hw[(size_t)c1.x * 32 + lane];
        uint2 u2 = hw[(size_t)c2.x * 32 + lane];
        uint2 u3 = hw[(size_t)c3.x * 32 + lane];
        float w0 = __int_as_float(c0.y), w1 = __int_as_float(c1.y);
        float w2 = __int_as_float(c2.y), w3 = __int_as_float(c3.y);
        float2 a0 = __half22float2(*(__half2*)&u0.x), b0 = __half22float2(*(__half2*)&u0.y);
        float2 a1 = __half22float2(*(__half2*)&u1.x), b1 = __half22float2(*(__half2*)&u1.y);
        float2 a2 = __half22float2(*(__half2*)&u2.x), b2 = __half22float2(*(__half2*)&u2.y);
        float2 a3 = __half22float2(*(__half2*)&u3.x), b3 = __half22float2(*(__half2*)&u3.y);
        acc.x += w0 * a0.x + w1 * a1.x + w2 * a2.x + w3 * a3.x;
        acc.y += w0 * a0.y + w1 * a1.y + w2 * a2.y + w3 * a3.y;
        acc.z += w0 * b0.x + w1 * b1.x + w2 * b2.x + w3 * b3.x;
        acc.w += w0 * b0.y + w1 * b1.y + w2 * b2.y + w3 * b3.y;
    }
    if (e + 1 < e1) {
        int2 c0 = cew[e], c1 = cew[e + 1];
        uint2 u0 = hw[(size_t)c0.x * 32 + lane];
        uint2 u1 = hw[(size_t)c1.x * 32 + lane];
        float w0 = __int_as_float(c0.y), w1 = __int_as_float(c1.y);
        float2 a0 = __half22float2(*(__half2*)&u0.x), b0 = __half22float2(*(__half2*)&u0.y);
        float2 a1 = __half22float2(*(__half2*)&u1.x), b1 = __half22float2(*(__half2*)&u1.y);
        acc.x += w0 * a0.x + w1 * a1.x;
        acc.y += w0 * a0.y + w1 * a1.y;
        acc.z += w0 * b0.x + w1 * b1.x;
        acc.w += w0 * b0.y + w1 * b1.y;
        e += 2;
    }
    if (e < e1) {
        int2 c0 = cew[e];
        uint2 u0 = hw[(size_t)c0.x * 32 + lane];
        float w0 = __int_as_float(c0.y);
        float2 a0 = __half22float2(*(__half2*)&u0.x), b0 = __half22float2(*(__half2*)&u0.y);
        acc.x += w0 * a0.x; acc.y += w0 * a0.y;
        acc.z += w0 * b0.x; acc.w += w0 * b0.y;
    }
    float di = g_dinv[w];
    float sn = di * di;
    uint2 us = hw[(size_t)w * 32 + lane];
    float2 s0 = __half22float2(*(__half2*)&us.x), s1 = __half22float2(*(__half2*)&us.y);
    const float4* b4 = (const float4*)bias;
    float4 b = b4[lane];
    float4 r;
    r.x = fmaxf(acc.x + sn * s0.x + b.x, 0.f);
    r.y = fmaxf(acc.y + sn * s0.y + b.y, 0.f);
    r.z = fmaxf(acc.z + sn * s1.x + b.z, 0.f);
    r.w = fmaxf(acc.w + sn * s1.y + b.w, 0.f);
    ((float4*)(g_H + (size_t)l * NN * CDIM))[(size_t)w * 32 + lane] = r;
}

// ---------------- final: softmax over layers + layer-mix + out GEMM ----------------
__global__ __launch_bounds__(256) void final_kernel(const float* __restrict__ Wout,
                                                    const float* __restrict__ bout,
                                                    float* __restrict__ out) {
    __shared__ float At[128][33];
    __shared__ float Ws[128][40];
    __shared__ float sal[128][4];
    int tid = threadIdx.x;
    int m0 = blockIdx.x * 128;

    if (tid < 128) {
        int row = m0 + tid;
        float s0 = 0.f, s1 = 0.f, s2 = 0.f, s3 = 0.f;
        if (row < NN) {
            s0 = g_scores[(size_t)row * 4 + 0];
            s1 = g_scores[(size_t)row * 4 + 1];
            s2 = g_scores[(size_t)row * 4 + 2];
            s3 = g_scores[(size_t)row * 4 + 3];
        }
        float mx = fmaxf(fmaxf(s0, s1), fmaxf(s2, s3));
        float e0 = expf(s0 - mx), e1 = expf(s1 - mx), e2 = expf(s2 - mx), e3 = expf(s3 - mx);
        float inv = 1.0f / (e0 + e1 + e2 + e3);
        sal[tid][0] = e0 * inv; sal[tid][1] = e1 * inv;
        sal[tid][2] = e2 * inv; sal[tid][3] = e3 * inv;
    }
    for (int i = tid; i < 128 * 40; i += 256) Ws[i / 40][i % 40] = Wout[i];
    __syncthreads();

    float acc[4][5];
#pragma unroll
    for (int r = 0; r < 4; ++r)
#pragma unroll
        for (int j = 0; j < 5; ++j) acc[r][j] = 0.f;

    int ty = tid >> 3, tx = tid & 7;
    const size_t LSTR = (size_t)NN * CDIM;

    for (int kc = 0; kc < 128; kc += 32) {
#pragma unroll
        for (int it = 0; it < 4; ++it) {
            int idx = it * 256 + tid;
            int m = idx >> 3, kq = idx & 7;
            int row = m0 + m;
            float4 v = make_float4(0.f, 0.f, 0.f, 0.f);
            if (row < NN) {
                size_t off = (size_t)row * 128 + kc + kq * 4;
                float a0 = sal[m][0], a1 = sal[m][1], a2 = sal[m][2], a3 = sal[m][3];
                float4 h0 = *(const float4*)(g_H + off);
                float4 h1 = *(const float4*)(g_H + off + LSTR);
                float4 h2 = *(const float4*)(g_H + off + 2 * LSTR);
                float4 h3 = *(const float4*)(g_H + off + 3 * LSTR);
                v.x = a0 * h0.x + a1 * h1.x + a2 * h2.x + a3 * h3.x;
                v.y = a0 * h0.y + a1 * h1.y + a2 * h2.y + a3 * h3.y;
                v.z = a0 * h0.z + a1 * h1.z + a2 * h2.z + a3 * h3.z;
                v.w = a0 * h0.w + a1 * h1.w + a2 * h2.w + a3 * h3.w;
            }
            At[m][kq * 4 + 0] = v.x; At[m][kq * 4 + 1] = v.y;
            At[m][kq * 4 + 2] = v.z; At[m][kq * 4 + 3] = v.w;
        }
        __syncthreads();
#pragma unroll
        for (int kk = 0; kk < 32; ++kk) {
            float a[4];
#pragma unroll
            for (int rr = 0; rr < 4; ++rr) a[rr] = At[ty * 4 + rr][kk];
            float b[5];
#pragma unroll
            for (int j = 0; j < 5; ++j) b[j] = Ws[kc + kk][tx * 5 + j];
#pragma unroll
            for (int rr = 0; rr < 4; ++rr)
#pragma unroll
                for (int j = 0; j < 5; ++j) acc[rr][j] += a[rr] * b[j];
        }
        __syncthreads();
    }

#pragma unroll
    for (int rr = 0; rr < 4; ++rr) {
        int row = m0 + ty * 4 + rr;
        if (row < NN) {
#pragma unroll
            for (int j = 0; j < 5; ++j) {
                int col = tx * 5 + j;
                out[(size_t)row * NCLASS + col] = acc[rr][j] + bout[col];
            }
        }
    }
}

// ---------------- launch ----------------
static const void* find_by_size(void* const* d_in, const int* in_sizes, int n_in,
                                long long want, const void* fallback) {
    for (int i = 0; i < n_in; ++i)
        if ((long long)in_sizes[i] == want) return d_in[i];
    return fallback;
}

extern "C" void kernel_launch(void* const* d_in, const int* in_sizes, int n_in,
                              void* d_out, int out_size) {
    const float* x     = (const float*)find_by_size(d_in, in_sizes, n_in, (long long)NN * CDIM, d_in[0]);
    const void*  ei    =               find_by_size(d_in, in_sizes, n_in, 2LL * NE,            d_in[1]);
    const float* convW = (const float*)find_by_size(d_in, in_sizes, n_in, (long long)NLAYER * CDIM * CDIM, d_in[2]);
    const float* convb = (const float*)find_by_size(d_in, in_sizes, n_in, (long long)NLAYER * CDIM, d_in[3]);
    const float* W_att = (const float*)find_by_size(d_in, in_sizes, n_in, (long long)CDIM * CDIM, d_in[4]);
    const float* a_att = (const float*)find_by_size(d_in, in_sizes, n_in, (long long)CDIM, d_in[5]);
    const float* W_out = (const float*)find_by_size(d_in, in_sizes, n_in, (long long)CDIM * NCLASS, d_in[6]);
    const float* b_out = (const float*)find_by_size(d_in, in_sizes, n_in, (long long)NCLASS, d_in[7]);
    float*       out   = (float*)d_out;

    zero_kernel<<<(NN + 255) / 256, 256>>>(ei);
    hist_kernel<<<(NE + 255) / 256, 256>>>(ei);
    scan1_kernel<<<49, 1024>>>();
    scan3_kernel<<<49, 1024>>>();
    scatter_kernel<<<(NE + 255) / 256, 256>>>(ei);
    bprep_kernel<<<(5 * 8192 + 255) / 256, 256>>>(convW, W_att);

    const int GB = (NN + 127) / 128;  // 391
    // layer 0: conv only (A = x)
    gemm_kernel<<<GB, 256>>>(x, a_att, -1, 0, 0, GB);
    agg_kernel<<<(NN * 32 + 255) / 256, 256>>>(convb, 0);
    // layers 1..3: fused conv(l) + att(l-1), both reading g_H[l-1]
    for (int l = 1; l < NLAYER; ++l) {
        gemm_kernel<<<2 * GB, 256>>>(x, a_att, l - 1, l, l - 1, GB);
        agg_kernel<<<(NN * 32 + 255) / 256, 256>>>(convb, l);
    }
    // att for the last layer
    gemm_kernel<<<GB, 256>>>(x, a_att, 3, 0, 3, 0);
    final_kernel<<<GB, 256>>>(W_out, b_out, out);
}